// round 5
// baseline (speedup 1.0000x reference)
#include <cuda_runtime.h>
#include <cuda_fp16.h>
#include <cstdint>
#include <math.h>

#define Hh   16
#define Dh   64
#define Bn   2
#define Sn   2048
#define Cn   1024
#define Mrows (Bn*Sn)          // 4096

// ---------------- scratch (__device__ globals; no allocation) --------------
__device__ __half g_xh  [(size_t)Mrows*Cn];
__device__ __half g_wqT [(size_t)Cn*Cn];
__device__ __half g_wkT [(size_t)Cn*Cn];
__device__ __half g_wvT [(size_t)Cn*Cn];
__device__ __half g_woT [(size_t)Cn*Cn];
__device__ __half g_qh  [(size_t)Bn*Hh*Sn*Dh];
__device__ __half g_kh  [(size_t)Bn*Hh*Sn*Dh];
__device__ __half g_vh  [(size_t)Bn*Hh*Sn*Dh];
__device__ __half g_attnh[(size_t)Mrows*Cn];

// ---------------- PTX helpers (base-arch only: sm_80 level) ----------------
__device__ __forceinline__ uint32_t smem_u32(const void* p) {
    uint32_t a;
    asm("{ .reg .u64 t; cvta.to.shared.u64 t, %1; cvt.u32.u64 %0, t; }"
        : "=r"(a) : "l"(p));
    return a;
}
#define CP16(dst, src) \
    asm volatile("cp.async.cg.shared.global [%0], [%1], 16;" :: "r"(dst), "l"(src))
#define CPCOMMIT() asm volatile("cp.async.commit_group;" ::: "memory")
template<int N> __device__ __forceinline__ void cpwait() {
    asm volatile("cp.async.wait_group %0;" :: "n"(N) : "memory");
}
#define LDSM4(d0,d1,d2,d3,addr) \
    asm volatile("ldmatrix.sync.aligned.m8n8.x4.shared.b16 {%0,%1,%2,%3}, [%4];" \
        : "=r"(d0),"=r"(d1),"=r"(d2),"=r"(d3) : "r"(addr))
#define LDSM4T(d0,d1,d2,d3,addr) \
    asm volatile("ldmatrix.sync.aligned.m8n8.x4.trans.shared.b16 {%0,%1,%2,%3}, [%4];" \
        : "=r"(d0),"=r"(d1),"=r"(d2),"=r"(d3) : "r"(addr))

__device__ __forceinline__ void mma16816(float c[4], const uint32_t a[4],
                                         uint32_t b0, uint32_t b1) {
    asm volatile(
        "mma.sync.aligned.m16n8k16.row.col.f32.f16.f16.f32 "
        "{%0,%1,%2,%3},{%4,%5,%6,%7},{%8,%9},{%0,%1,%2,%3};"
        : "+f"(c[0]), "+f"(c[1]), "+f"(c[2]), "+f"(c[3])
        : "r"(a[0]), "r"(a[1]), "r"(a[2]), "r"(a[3]), "r"(b0), "r"(b1));
}
__device__ __forceinline__ uint32_t packh2(float lo, float hi) {
    __half2 h = __floats2half2_rn(lo, hi);
    return *reinterpret_cast<uint32_t*>(&h);
}

// ---------------------------------------------------------------------------
// convert kernels
// ---------------------------------------------------------------------------
__global__ __launch_bounds__(256) void convert_x(const float* __restrict__ x) {
    size_t i = ((size_t)blockIdx.x * 256 + threadIdx.x) * 8;
    float4 v0 = *(const float4*)(x + i);
    float4 v1 = *(const float4*)(x + i + 4);
    uint4 o;
    o.x = packh2(v0.x, v0.y); o.y = packh2(v0.z, v0.w);
    o.z = packh2(v1.x, v1.y); o.w = packh2(v1.z, v1.w);
    *(uint4*)(&g_xh[i]) = o;
}

// transpose fp32 [R][C] -> half [C][R];  grid.z batches (stride R*C both sides)
__global__ __launch_bounds__(256) void transpose_cvt(const float* __restrict__ in,
                                                     int which, int R, int C) {
    __half* out = (which == 0) ? g_wqT : (which == 1) ? g_wkT
                 : (which == 2) ? g_wvT : g_woT;
    in  += (size_t)blockIdx.z * R * C;
    out += (size_t)blockIdx.z * R * C;
    __shared__ float t[32][33];
    int c0 = blockIdx.x * 32, r0 = blockIdx.y * 32;
    int tx = threadIdx.x, ty = threadIdx.y;
    #pragma unroll
    for (int i = 0; i < 4; i++)
        t[ty + 8*i][tx] = in[(size_t)(r0 + ty + 8*i) * C + c0 + tx];
    __syncthreads();
    #pragma unroll
    for (int i = 0; i < 4; i++)
        out[(size_t)(c0 + ty + 8*i) * R + r0 + tx] = __float2half(t[tx][ty + 8*i]);
}

// ---------------------------------------------------------------------------
// HMMA GEMM: C[M=4096][N=1024] = A[M][K=1024] * B[N][K]^T  (half in, f32 acc)
// 128x128 block tile, BK=64 halves (128B rows, chunk^row&7 swizzle),
// 8 warps (2x4), warp tile 64x32, cp.async double buffer.
// MODE 0: A=g_xh, B=W{q,k,v}T by blockIdx.z, out -> g_{q,k,v}h [b,h,s,d]
// MODE 1: A=g_attnh, B=g_woT, out -> f32 + bias
// ---------------------------------------------------------------------------
#define GEMM_SMEM 65536

template<int MODE>
__global__ __launch_bounds__(256) void gemm_h(const float* __restrict__ bo,
                                              float* __restrict__ outf)
{
    extern __shared__ __align__(16) char sm[];
    const uint32_t sb = smem_u32(sm);
    const int tid = threadIdx.x;
    const int m0 = blockIdx.y * 128, n0 = blockIdx.x * 128;
    const int z = MODE ? 0 : blockIdx.z;
    const __half* A = MODE ? g_attnh : g_xh;
    const __half* B = MODE ? g_woT : (z == 0 ? g_wqT : (z == 1 ? g_wkT : g_wvT));

    float acc[4][4][4];
    #pragma unroll
    for (int i = 0; i < 4; i++)
        #pragma unroll
        for (int j = 0; j < 4; j++)
            #pragma unroll
            for (int r = 0; r < 4; r++) acc[i][j][r] = 0.f;

    const int l = tid & 31, w = tid >> 5, wm = w >> 2, wn = w & 3;
    const int arow_b = wm * 64 + (l & 7) + 8 * ((l >> 3) & 1);
    const int acb = l >> 4;
    const int brow_b = wn * 32 + (l & 7) + 8 * (l >> 4);
    const int bcb = (l >> 3) & 1;

    auto load = [&](int buf, int k0) {
        #pragma unroll
        for (int t = 0; t < 4; t++) {
            int idx = tid + t * 256;
            int row = idx >> 3, c = idx & 7;
            uint32_t sw = (uint32_t)((c ^ (row & 7)) * 16);
            CP16(sb + buf * 16384 + row * 128 + sw,
                 A + (size_t)(m0 + row) * Cn + k0 + c * 8);
            CP16(sb + 32768 + buf * 16384 + row * 128 + sw,
                 B + (size_t)(n0 + row) * Cn + k0 + c * 8);
        }
    };

    load(0, 0); CPCOMMIT();

    for (int it = 0; it < 16; it++) {
        const int buf = it & 1;
        if (it < 15) { load(buf ^ 1, (it + 1) * 64); CPCOMMIT(); cpwait<1>(); }
        else         cpwait<0>();
        __syncthreads();
        const uint32_t Ab = sb + buf * 16384;
        const uint32_t Bb = sb + 32768 + buf * 16384;
        #pragma unroll
        for (int ks = 0; ks < 4; ks++) {
            uint32_t a[4][4], bf[4][2];
            #pragma unroll
            for (int mf = 0; mf < 4; mf++) {
                int r = arow_b + mf * 16;
                LDSM4(a[mf][0], a[mf][1], a[mf][2], a[mf][3],
                      Ab + r * 128 + (((ks * 2 + acb) ^ (r & 7)) * 16));
            }
            #pragma unroll
            for (int p = 0; p < 2; p++) {
                int r = brow_b + p * 16;
                LDSM4(bf[2*p][0], bf[2*p][1], bf[2*p+1][0], bf[2*p+1][1],
                      Bb + r * 128 + (((ks * 2 + bcb) ^ (r & 7)) * 16));
            }
            #pragma unroll
            for (int mf = 0; mf < 4; mf++)
                #pragma unroll
                for (int nf = 0; nf < 4; nf++)
                    mma16816(acc[mf][nf], a[mf], bf[nf][0], bf[nf][1]);
        }
        __syncthreads();
    }

    // epilogue
    const int g = l >> 2, t2 = (l & 3) * 2;
    if (MODE == 0) {
        const float sc = (z == 0) ? 0.125f : 1.0f;   // fold 1/sqrt(D) into q
        __half* O = (z == 0) ? g_qh : (z == 1) ? g_kh : g_vh;
        #pragma unroll
        for (int mf = 0; mf < 4; mf++) {
            int row = m0 + wm * 64 + mf * 16 + g;
            int b_ = row >> 11, s = row & (Sn - 1);
            #pragma unroll
            for (int nf = 0; nf < 4; nf++) {
                int col = n0 + wn * 32 + nf * 8 + t2;
                int h = col >> 6, d = col & 63;
                size_t i0 = (((size_t)b_ * Hh + h) * Sn + s) * Dh + d;
                *(__half2*)(O + i0) =
                    __floats2half2_rn(acc[mf][nf][0] * sc, acc[mf][nf][1] * sc);
                *(__half2*)(O + i0 + 8 * Dh) =
                    __floats2half2_rn(acc[mf][nf][2] * sc, acc[mf][nf][3] * sc);
            }
        }
    } else {
        #pragma unroll
        for (int mf = 0; mf < 4; mf++) {
            int row = m0 + wm * 64 + mf * 16 + g;
            #pragma unroll
            for (int nf = 0; nf < 4; nf++) {
                int col = n0 + wn * 32 + nf * 8 + t2;
                float b0v = bo[col], b1v = bo[col + 1];
                *(float2*)(outf + (size_t)row * Cn + col) =
                    make_float2(acc[mf][nf][0] + b0v, acc[mf][nf][1] + b1v);
                *(float2*)(outf + (size_t)(row + 8) * Cn + col) =
                    make_float2(acc[mf][nf][2] + b0v, acc[mf][nf][3] + b1v);
            }
        }
    }
}

// ---------------------------------------------------------------------------
// HMMA causal flash attention.  Br=128, Bc=64, D=64.  8 warps, each warp owns
// a 16-row strip (softmax rows never cross warps).  P acc fragments re-pack
// directly into A fragments of the P*V mma (no shuffle, no smem round trip).
// q pre-scaled by 0.125 at projection time.
// ---------------------------------------------------------------------------
#define FLASH_SMEM 49152   // Q 16K + (K 8K + V 8K) * 2 bufs

__global__ __launch_bounds__(256) void flash_h()
{
    extern __shared__ __align__(16) char sm[];
    const uint32_t sb = smem_u32(sm);
    const int tid = threadIdx.x;
    const int l = tid & 31, w = tid >> 5;
    const int bh = blockIdx.y, qt = blockIdx.x;
    const int qs0 = qt * 128;

    const __half* Qb = g_qh + (size_t)bh * Sn * Dh;
    const __half* Kb = g_kh + (size_t)bh * Sn * Dh;
    const __half* Vb = g_vh + (size_t)bh * Sn * Dh;

    auto load_kv = [&](int buf, int ks0) {
        #pragma unroll
        for (int t = 0; t < 4; t++) {
            int idx = tid + t * 256;
            int which = idx >> 9;            // 0=K, 1=V
            int r = (idx >> 3) & 63, c = idx & 7;
            const __half* src = (which ? Vb : Kb) + (size_t)(ks0 + r) * Dh + c * 8;
            uint32_t dst = sb + 16384 + buf * 16384 + which * 8192
                         + r * 128 + ((c ^ (r & 7)) * 16);
            CP16(dst, src);
        }
    };

    // prologue: Q tile + first KV tile in one group
    #pragma unroll
    for (int t = 0; t < 4; t++) {
        int idx = tid + t * 256;
        int row = idx >> 3, c = idx & 7;
        CP16(sb + row * 128 + ((c ^ (row & 7)) * 16),
             Qb + (size_t)(qs0 + row) * Dh + c * 8);
    }
    load_kv(0, 0);
    CPCOMMIT();

    uint32_t qf[4][4];
    float o[8][4];
    #pragma unroll
    for (int i = 0; i < 8; i++)
        #pragma unroll
        for (int j = 0; j < 4; j++) o[i][j] = 0.f;
    float m0_ = -1e30f, m1_ = -1e30f, l0_ = 0.f, l1_ = 0.f;

    const int g = l >> 2, t2 = (l & 3) * 2;
    const int arow = (l & 7) + 8 * ((l >> 3) & 1);  // Q / V row pattern
    const int acb  = l >> 4;
    const int brow = (l & 7) + 8 * (l >> 4);        // K row pattern
    const int bcb  = (l >> 3) & 1;

    const int nt = 2 * qt + 2;
    for (int jt = 0; jt < nt; jt++) {
        const int buf = jt & 1;
        if (jt + 1 < nt) { load_kv(buf ^ 1, (jt + 1) * 64); CPCOMMIT(); cpwait<1>(); }
        else             cpwait<0>();
        __syncthreads();

        if (jt == 0) {
            #pragma unroll
            for (int ks = 0; ks < 4; ks++) {
                int r = w * 16 + arow;
                LDSM4(qf[ks][0], qf[ks][1], qf[ks][2], qf[ks][3],
                      sb + r * 128 + (((ks * 2 + acb) ^ (r & 7)) * 16));
            }
        }
        const uint32_t Kbase = sb + 16384 + buf * 16384;
        const uint32_t Vbase = Kbase + 8192;

        // S = Q K^T  (16 x 64 per warp)
        float s[8][4];
        #pragma unroll
        for (int i = 0; i < 8; i++)
            #pragma unroll
            for (int j = 0; j < 4; j++) s[i][j] = 0.f;
        #pragma unroll
        for (int ks = 0; ks < 4; ks++) {
            uint32_t kb[8][2];
            #pragma unroll
            for (int p = 0; p < 4; p++) {
                int r = p * 16 + brow;
                LDSM4(kb[2*p][0], kb[2*p][1], kb[2*p+1][0], kb[2*p+1][1],
                      Kbase + r * 128 + (((ks * 2 + bcb) ^ (r & 7)) * 16));
            }
            #pragma unroll
            for (int nf = 0; nf < 8; nf++)
                mma16816(s[nf], qf[ks], kb[nf][0], kb[nf][1]);
        }

        // causal mask (diag tiles only)
        const int ks0 = jt * 64;
        const int rg = qs0 + w * 16 + g;
        if (jt >= nt - 2) {
            #pragma unroll
            for (int nf = 0; nf < 8; nf++) {
                int c0 = ks0 + nf * 8 + t2;
                if (c0     > rg    ) s[nf][0] = -1e30f;
                if (c0 + 1 > rg    ) s[nf][1] = -1e30f;
                if (c0     > rg + 8) s[nf][2] = -1e30f;
                if (c0 + 1 > rg + 8) s[nf][3] = -1e30f;
            }
        }

        // online softmax (rows g and g+8)
        float x0 = -1e30f, x1 = -1e30f;
        #pragma unroll
        for (int nf = 0; nf < 8; nf++) {
            x0 = fmaxf(x0, fmaxf(s[nf][0], s[nf][1]));
            x1 = fmaxf(x1, fmaxf(s[nf][2], s[nf][3]));
        }
        x0 = fmaxf(x0, __shfl_xor_sync(0xffffffffu, x0, 1));
        x0 = fmaxf(x0, __shfl_xor_sync(0xffffffffu, x0, 2));
        x1 = fmaxf(x1, __shfl_xor_sync(0xffffffffu, x1, 1));
        x1 = fmaxf(x1, __shfl_xor_sync(0xffffffffu, x1, 2));
        float mn0 = fmaxf(m0_, x0), mn1 = fmaxf(m1_, x1);
        float al0 = __expf(m0_ - mn0), al1 = __expf(m1_ - mn1);
        m0_ = mn0; m1_ = mn1;
        float rs0 = 0.f, rs1 = 0.f;
        #pragma unroll
        for (int nf = 0; nf < 8; nf++) {
            s[nf][0] = __expf(s[nf][0] - mn0);
            s[nf][1] = __expf(s[nf][1] - mn0);
            s[nf][2] = __expf(s[nf][2] - mn1);
            s[nf][3] = __expf(s[nf][3] - mn1);
            rs0 += s[nf][0] + s[nf][1];
            rs1 += s[nf][2] + s[nf][3];
        }
        l0_ = l0_ * al0 + rs0;
        l1_ = l1_ * al1 + rs1;
        #pragma unroll
        for (int df = 0; df < 8; df++) {
            o[df][0] *= al0; o[df][1] *= al0;
            o[df][2] *= al1; o[df][3] *= al1;
        }

        // pack P acc -> A fragments (layout identity)
        uint32_t pf[4][4];
        #pragma unroll
        for (int ki = 0; ki < 4; ki++) {
            pf[ki][0] = packh2(s[2*ki][0],   s[2*ki][1]);
            pf[ki][1] = packh2(s[2*ki][2],   s[2*ki][3]);
            pf[ki][2] = packh2(s[2*ki+1][0], s[2*ki+1][1]);
            pf[ki][3] = packh2(s[2*ki+1][2], s[2*ki+1][3]);
        }

        // O += P V   (V via ldmatrix.trans on [j][d])
        #pragma unroll
        for (int ki = 0; ki < 4; ki++) {
            uint32_t vb[8][2];
            #pragma unroll
            for (int p = 0; p < 4; p++) {
                int r = ki * 16 + arow;
                LDSM4T(vb[2*p][0], vb[2*p][1], vb[2*p+1][0], vb[2*p+1][1],
                       Vbase + r * 128 + (((p * 2 + acb) ^ (r & 7)) * 16));
            }
            #pragma unroll
            for (int df = 0; df < 8; df++)
                mma16816(o[df], pf[ki], vb[df][0], vb[df][1]);
        }
        __syncthreads();
    }

    // epilogue: reduce l over the 4-lane row group, normalize, write half
    float ls0 = l0_, ls1 = l1_;
    ls0 += __shfl_xor_sync(0xffffffffu, ls0, 1);
    ls0 += __shfl_xor_sync(0xffffffffu, ls0, 2);
    ls1 += __shfl_xor_sync(0xffffffffu, ls1, 1);
    ls1 += __shfl_xor_sync(0xffffffffu, ls1, 2);
    const float inv0 = 1.f / ls0, inv1 = 1.f / ls1;
    const int b_ = bh >> 4, h_ = bh & 15;
    const int r0 = qs0 + w * 16 + g;
    #pragma unroll
    for (int df = 0; df < 8; df++) {
        int col = h_ * 64 + df * 8 + t2;
        *(__half2*)(g_attnh + (size_t)(b_ * Sn + r0) * Cn + col) =
            __floats2half2_rn(o[df][0] * inv0, o[df][1] * inv0);
        *(__half2*)(g_attnh + (size_t)(b_ * Sn + r0 + 8) * Cn + col) =
            __floats2half2_rn(o[df][2] * inv1, o[df][3] * inv1);
    }
}

// ---------------------------------------------------------------------------
extern "C" void kernel_launch(void* const* d_in, const int* in_sizes, int n_in,
                              void* d_out, int out_size)
{
    (void)in_sizes; (void)n_in; (void)out_size;
    const float* x  = (const float*)d_in[0];
    const float* Wq = (const float*)d_in[1];
    const float* Wk = (const float*)d_in[2];
    const float* Wv = (const float*)d_in[3];
    const float* Wo = (const float*)d_in[4];
    const float* bo = (const float*)d_in[5];
    float* out = (float*)d_out;

    cudaFuncSetAttribute(gemm_h<0>, cudaFuncAttributeMaxDynamicSharedMemorySize, GEMM_SMEM);
    cudaFuncSetAttribute(gemm_h<1>, cudaFuncAttributeMaxDynamicSharedMemorySize, GEMM_SMEM);
    cudaFuncSetAttribute(flash_h,   cudaFuncAttributeMaxDynamicSharedMemorySize, FLASH_SMEM);

    convert_x<<<Mrows * Cn / (256 * 8), 256>>>(x);
    transpose_cvt<<<dim3(2, 32, 16), dim3(32, 8)>>>(Wq, 0, Cn, Dh);
    transpose_cvt<<<dim3(2, 32, 16), dim3(32, 8)>>>(Wk, 1, Cn, Dh);
    transpose_cvt<<<dim3(2, 32, 16), dim3(32, 8)>>>(Wv, 2, Cn, Dh);
    transpose_cvt<<<dim3(32, 32, 1), dim3(32, 8)>>>(Wo, 3, Cn, Cn);

    gemm_h<0><<<dim3(Cn / 128, Mrows / 128, 3), 256, GEMM_SMEM>>>(nullptr, nullptr);
    flash_h<<<dim3(Sn / 128, Bn * Hh), 256, FLASH_SMEM>>>();
    gemm_h<1><<<dim3(Cn / 128, Mrows / 128, 1), 256, GEMM_SMEM>>>(bo, out);
}

// round 6
// speedup vs baseline: 1.0513x; 1.0513x over previous
#include <cuda_runtime.h>
#include <cuda_fp16.h>
#include <cstdint>
#include <math.h>

#define Hh   16
#define Dh   64
#define Bn   2
#define Sn   2048
#define Cn   1024
#define Mrows (Bn*Sn)          // 4096

// ---------------- scratch (__device__ globals; no allocation) --------------
__device__ __half g_xh  [(size_t)Mrows*Cn];
__device__ __half g_wqT [(size_t)Cn*Cn];
__device__ __half g_wkT [(size_t)Cn*Cn];
__device__ __half g_wvT [(size_t)Cn*Cn];
__device__ __half g_woT [(size_t)Cn*Cn];
__device__ __half g_qh  [(size_t)Bn*Hh*Sn*Dh];
__device__ __half g_kh  [(size_t)Bn*Hh*Sn*Dh];
__device__ __half g_vh  [(size_t)Bn*Hh*Sn*Dh];
__device__ __half g_attnh[(size_t)Mrows*Cn];

// ---------------- PTX helpers (base-arch sm_80/sm_75 level only) -----------
__device__ __forceinline__ uint32_t smem_u32(const void* p) {
    uint32_t a;
    asm("{ .reg .u64 t; cvta.to.shared.u64 t, %1; cvt.u32.u64 %0, t; }"
        : "=r"(a) : "l"(p));
    return a;
}
#define CP16(dst, src) \
    asm volatile("cp.async.cg.shared.global [%0], [%1], 16;" :: "r"(dst), "l"(src))
#define CPCOMMIT() asm volatile("cp.async.commit_group;" ::: "memory")
template<int N> __device__ __forceinline__ void cpwait() {
    asm volatile("cp.async.wait_group %0;" :: "n"(N) : "memory");
}
#define LDSM4(d0,d1,d2,d3,addr) \
    asm volatile("ldmatrix.sync.aligned.m8n8.x4.shared.b16 {%0,%1,%2,%3}, [%4];" \
        : "=r"(d0),"=r"(d1),"=r"(d2),"=r"(d3) : "r"(addr))
#define LDSM4T(d0,d1,d2,d3,addr) \
    asm volatile("ldmatrix.sync.aligned.m8n8.x4.trans.shared.b16 {%0,%1,%2,%3}, [%4];" \
        : "=r"(d0),"=r"(d1),"=r"(d2),"=r"(d3) : "r"(addr))

__device__ __forceinline__ void mma16816(float c[4], const uint32_t a[4],
                                         uint32_t b0, uint32_t b1) {
    asm volatile(
        "mma.sync.aligned.m16n8k16.row.col.f32.f16.f16.f32 "
        "{%0,%1,%2,%3},{%4,%5,%6,%7},{%8,%9},{%0,%1,%2,%3};"
        : "+f"(c[0]), "+f"(c[1]), "+f"(c[2]), "+f"(c[3])
        : "r"(a[0]), "r"(a[1]), "r"(a[2]), "r"(a[3]), "r"(b0), "r"(b1));
}
__device__ __forceinline__ uint32_t packh2(float lo, float hi) {
    __half2 h = __floats2half2_rn(lo, hi);
    return *reinterpret_cast<uint32_t*>(&h);
}
__device__ __forceinline__ float ex2f(float x) {
    float y; asm("ex2.approx.f32 %0, %1;" : "=f"(y) : "f"(x)); return y;
}
__device__ __forceinline__ uint32_t h2ex2(uint32_t x) {
    uint32_t y; asm("ex2.approx.f16x2 %0, %1;" : "=r"(y) : "r"(x)); return y;
}

// ---------------------------------------------------------------------------
// convert kernels
// ---------------------------------------------------------------------------
__global__ __launch_bounds__(256) void convert_x(const float* __restrict__ x) {
    size_t i = ((size_t)blockIdx.x * 256 + threadIdx.x) * 8;
    float4 v0 = *(const float4*)(x + i);
    float4 v1 = *(const float4*)(x + i + 4);
    uint4 o;
    o.x = packh2(v0.x, v0.y); o.y = packh2(v0.z, v0.w);
    o.z = packh2(v1.x, v1.y); o.w = packh2(v1.z, v1.w);
    *(uint4*)(&g_xh[i]) = o;
}

// transpose fp32 [R][C] -> half [C][R];  grid.z batches (stride R*C both sides)
__global__ __launch_bounds__(256) void transpose_cvt(const float* __restrict__ in,
                                                     int which, int R, int C) {
    __half* out = (which == 0) ? g_wqT : (which == 1) ? g_wkT
                 : (which == 2) ? g_wvT : g_woT;
    in  += (size_t)blockIdx.z * R * C;
    out += (size_t)blockIdx.z * R * C;
    __shared__ float t[32][33];
    int c0 = blockIdx.x * 32, r0 = blockIdx.y * 32;
    int tx = threadIdx.x, ty = threadIdx.y;
    #pragma unroll
    for (int i = 0; i < 4; i++)
        t[ty + 8*i][tx] = in[(size_t)(r0 + ty + 8*i) * C + c0 + tx];
    __syncthreads();
    #pragma unroll
    for (int i = 0; i < 4; i++)
        out[(size_t)(c0 + ty + 8*i) * R + r0 + tx] = __float2half(t[tx][ty + 8*i]);
}

// ---------------------------------------------------------------------------
// HMMA GEMM: C[M=4096][N=1024] = A[M][K=1024] * B[N][K]^T  (half in, f32 acc)
// 128x128 block tile, BK=64 (128B rows, chunk^row&7 swizzle), 8 warps (2x4),
// warp tile 64x32, 3-stage cp.async pipeline, one __syncthreads per K-step.
// MODE 0: A=g_xh, B=W{q,k,v}T by blockIdx.z, out -> g_{q,k,v}h [b,h,s,d]
//         (q epilogue folds 0.125*log2e so flash works in log2 domain)
// MODE 1: A=g_attnh, B=g_woT, out -> f32 + bias
// ---------------------------------------------------------------------------
#define GSTAGES 3
#define GEMM_SMEM (GSTAGES * 32768)   // 96 KB

template<int MODE>
__global__ __launch_bounds__(256) void gemm_h(const float* __restrict__ bo,
                                              float* __restrict__ outf)
{
    extern __shared__ __align__(16) char sm[];
    const uint32_t sb = smem_u32(sm);
    const int tid = threadIdx.x;
    const int m0 = blockIdx.y * 128, n0 = blockIdx.x * 128;
    const int z = MODE ? 0 : blockIdx.z;
    const __half* A = MODE ? g_attnh : g_xh;
    const __half* B = MODE ? g_woT : (z == 0 ? g_wqT : (z == 1 ? g_wkT : g_wvT));

    float acc[4][4][4];
    #pragma unroll
    for (int i = 0; i < 4; i++)
        #pragma unroll
        for (int j = 0; j < 4; j++)
            #pragma unroll
            for (int r = 0; r < 4; r++) acc[i][j][r] = 0.f;

    const int l = tid & 31, w = tid >> 5, wm = w >> 2, wn = w & 3;
    const int arow_b = wm * 64 + (l & 7) + 8 * ((l >> 3) & 1);
    const int acb = l >> 4;
    const int brow_b = wn * 32 + (l & 7) + 8 * (l >> 4);
    const int bcb = (l >> 3) & 1;

    auto load = [&](int buf, int k0) {
        #pragma unroll
        for (int t = 0; t < 4; t++) {
            int idx = tid + t * 256;
            int row = idx >> 3, c = idx & 7;
            uint32_t sw = (uint32_t)((c ^ (row & 7)) * 16);
            CP16(sb + buf * 16384 + row * 128 + sw,
                 A + (size_t)(m0 + row) * Cn + k0 + c * 8);
            CP16(sb + GSTAGES * 16384 + buf * 16384 + row * 128 + sw,
                 B + (size_t)(n0 + row) * Cn + k0 + c * 8);
        }
    };

    load(0, 0);  CPCOMMIT();
    load(1, 64); CPCOMMIT();

    for (int it = 0; it < 16; it++) {
        cpwait<1>();
        __syncthreads();
        if (it + 2 < 16) load((it + 2) % GSTAGES, (it + 2) * 64);
        CPCOMMIT();

        const int buf = it % GSTAGES;
        const uint32_t Ab = sb + buf * 16384;
        const uint32_t Bb = sb + GSTAGES * 16384 + buf * 16384;
        #pragma unroll
        for (int ks = 0; ks < 4; ks++) {
            uint32_t a[4][4], bf[4][2];
            #pragma unroll
            for (int mf = 0; mf < 4; mf++) {
                int r = arow_b + mf * 16;
                LDSM4(a[mf][0], a[mf][1], a[mf][2], a[mf][3],
                      Ab + r * 128 + (((ks * 2 + acb) ^ (r & 7)) * 16));
            }
            #pragma unroll
            for (int p = 0; p < 2; p++) {
                int r = brow_b + p * 16;
                LDSM4(bf[2*p][0], bf[2*p][1], bf[2*p+1][0], bf[2*p+1][1],
                      Bb + r * 128 + (((ks * 2 + bcb) ^ (r & 7)) * 16));
            }
            #pragma unroll
            for (int mf = 0; mf < 4; mf++)
                #pragma unroll
                for (int nf = 0; nf < 4; nf++)
                    mma16816(acc[mf][nf], a[mf], bf[nf][0], bf[nf][1]);
        }
    }

    // epilogue
    const int g = l >> 2, t2 = (l & 3) * 2;
    if (MODE == 0) {
        // q scale: 1/sqrt(D) * log2(e)  (flash softmax runs in log2 domain)
        const float sc = (z == 0) ? 0.180336881f : 1.0f;
        __half* O = (z == 0) ? g_qh : (z == 1) ? g_kh : g_vh;
        #pragma unroll
        for (int mf = 0; mf < 4; mf++) {
            int row = m0 + wm * 64 + mf * 16 + g;
            int b_ = row >> 11, s = row & (Sn - 1);
            #pragma unroll
            for (int nf = 0; nf < 4; nf++) {
                int col = n0 + wn * 32 + nf * 8 + t2;
                int h = col >> 6, d = col & 63;
                size_t i0 = (((size_t)b_ * Hh + h) * Sn + s) * Dh + d;
                *(__half2*)(O + i0) =
                    __floats2half2_rn(acc[mf][nf][0] * sc, acc[mf][nf][1] * sc);
                *(__half2*)(O + i0 + 8 * Dh) =
                    __floats2half2_rn(acc[mf][nf][2] * sc, acc[mf][nf][3] * sc);
            }
        }
    } else {
        #pragma unroll
        for (int mf = 0; mf < 4; mf++) {
            int row = m0 + wm * 64 + mf * 16 + g;
            #pragma unroll
            for (int nf = 0; nf < 4; nf++) {
                int col = n0 + wn * 32 + nf * 8 + t2;
                float b0v = bo[col], b1v = bo[col + 1];
                *(float2*)(outf + (size_t)row * Cn + col) =
                    make_float2(acc[mf][nf][0] + b0v, acc[mf][nf][1] + b1v);
                *(float2*)(outf + (size_t)(row + 8) * Cn + col) =
                    make_float2(acc[mf][nf][2] + b0v, acc[mf][nf][3] + b1v);
            }
        }
    }
}

// ---------------------------------------------------------------------------
// HMMA causal flash attention, log2-domain softmax.
// Br=128, Bc=64, D=64.  8 warps, warp owns a 16-row strip.
// p = ex2.approx.f16x2 (packed halves feed the P*V A-fragments directly),
// row sums via an extra mma against a ones B-fragment (exact fp32, full-row).
// 3-stage cp.async KV pipeline; heavy CTAs (large qt) launch first.
// ---------------------------------------------------------------------------
#define FSTAGES 3
#define FLASH_SMEM (16384 + FSTAGES * 16384)   // Q + 3 KV stages = 64 KB

__global__ __launch_bounds__(256) void flash_h()
{
    extern __shared__ __align__(16) char sm[];
    const uint32_t sb = smem_u32(sm);
    const int tid = threadIdx.x;
    const int l = tid & 31, w = tid >> 5;
    const int bh = blockIdx.y;
    const int qt = gridDim.x - 1 - blockIdx.x;   // heavy tiles first
    const int qs0 = qt * 128;

    const __half* Qb = g_qh + (size_t)bh * Sn * Dh;
    const __half* Kb = g_kh + (size_t)bh * Sn * Dh;
    const __half* Vb = g_vh + (size_t)bh * Sn * Dh;

    auto load_kv = [&](int buf, int ks0) {
        #pragma unroll
        for (int t = 0; t < 4; t++) {
            int idx = tid + t * 256;
            int which = idx >> 9;            // 0=K, 1=V
            int r = (idx >> 3) & 63, c = idx & 7;
            const __half* src = (which ? Vb : Kb) + (size_t)(ks0 + r) * Dh + c * 8;
            uint32_t dst = sb + 16384 + buf * 16384 + which * 8192
                         + r * 128 + ((c ^ (r & 7)) * 16);
            CP16(dst, src);
        }
    };

    const int nt = 2 * qt + 2;

    // prologue: Q + KV(0) in group 0, KV(1) in group 1
    #pragma unroll
    for (int t = 0; t < 4; t++) {
        int idx = tid + t * 256;
        int row = idx >> 3, c = idx & 7;
        CP16(sb + row * 128 + ((c ^ (row & 7)) * 16),
             Qb + (size_t)(qs0 + row) * Dh + c * 8);
    }
    load_kv(0, 0);
    CPCOMMIT();
    load_kv(1, 64);   // nt >= 2 always
    CPCOMMIT();

    uint32_t qf[4][4];
    float o[8][4];
    #pragma unroll
    for (int i = 0; i < 8; i++)
        #pragma unroll
        for (int j = 0; j < 4; j++) o[i][j] = 0.f;
    float m0_ = -1e30f, m1_ = -1e30f, l0_ = 0.f, l1_ = 0.f;

    const int g = l >> 2, t2 = (l & 3) * 2;
    const int arow = (l & 7) + 8 * ((l >> 3) & 1);  // Q / V row pattern
    const int acb  = l >> 4;
    const int brow = (l & 7) + 8 * (l >> 4);        // K row pattern
    const int bcb  = (l >> 3) & 1;
    const uint32_t ONES2 = 0x3C003C00u;             // half2(1,1)

    for (int jt = 0; jt < nt; jt++) {
        cpwait<1>();
        __syncthreads();
        if (jt + 2 < nt) load_kv((jt + 2) % FSTAGES, (jt + 2) * 64);
        CPCOMMIT();

        if (jt == 0) {
            #pragma unroll
            for (int ks = 0; ks < 4; ks++) {
                int r = w * 16 + arow;
                LDSM4(qf[ks][0], qf[ks][1], qf[ks][2], qf[ks][3],
                      sb + r * 128 + (((ks * 2 + acb) ^ (r & 7)) * 16));
            }
        }
        const int buf = jt % FSTAGES;
        const uint32_t Kbase = sb + 16384 + buf * 16384;
        const uint32_t Vbase = Kbase + 8192;

        // S = Q K^T  (16 x 64 per warp), already in log2 domain
        float s[8][4];
        #pragma unroll
        for (int i = 0; i < 8; i++)
            #pragma unroll
            for (int j = 0; j < 4; j++) s[i][j] = 0.f;
        #pragma unroll
        for (int ks = 0; ks < 4; ks++) {
            uint32_t kb[8][2];
            #pragma unroll
            for (int p = 0; p < 4; p++) {
                int r = p * 16 + brow;
                LDSM4(kb[2*p][0], kb[2*p][1], kb[2*p+1][0], kb[2*p+1][1],
                      Kbase + r * 128 + (((ks * 2 + bcb) ^ (r & 7)) * 16));
            }
            #pragma unroll
            for (int nf = 0; nf < 8; nf++)
                mma16816(s[nf], qf[ks], kb[nf][0], kb[nf][1]);
        }

        // causal mask (diag tiles only)
        const int ks0 = jt * 64;
        const int rg = qs0 + w * 16 + g;
        if (jt >= nt - 2) {
            #pragma unroll
            for (int nf = 0; nf < 8; nf++) {
                int c0 = ks0 + nf * 8 + t2;
                if (c0     > rg    ) s[nf][0] = -1e30f;
                if (c0 + 1 > rg    ) s[nf][1] = -1e30f;
                if (c0     > rg + 8) s[nf][2] = -1e30f;
                if (c0 + 1 > rg + 8) s[nf][3] = -1e30f;
            }
        }

        // online softmax (rows g and g+8), log2 domain
        float x0 = -1e30f, x1 = -1e30f;
        #pragma unroll
        for (int nf = 0; nf < 8; nf++) {
            x0 = fmaxf(x0, fmaxf(s[nf][0], s[nf][1]));
            x1 = fmaxf(x1, fmaxf(s[nf][2], s[nf][3]));
        }
        x0 = fmaxf(x0, __shfl_xor_sync(0xffffffffu, x0, 1));
        x0 = fmaxf(x0, __shfl_xor_sync(0xffffffffu, x0, 2));
        x1 = fmaxf(x1, __shfl_xor_sync(0xffffffffu, x1, 1));
        x1 = fmaxf(x1, __shfl_xor_sync(0xffffffffu, x1, 2));
        float mn0 = fmaxf(m0_, x0), mn1 = fmaxf(m1_, x1);
        float al0 = ex2f(m0_ - mn0), al1 = ex2f(m1_ - mn1);
        m0_ = mn0; m1_ = mn1;

        // p = 2^(s - m) as packed half2 == A fragments of P*V
        uint32_t pf[4][4];
        #pragma unroll
        for (int ki = 0; ki < 4; ki++) {
            pf[ki][0] = h2ex2(packh2(s[2*ki][0]   - mn0, s[2*ki][1]   - mn0));
            pf[ki][1] = h2ex2(packh2(s[2*ki][2]   - mn1, s[2*ki][3]   - mn1));
            pf[ki][2] = h2ex2(packh2(s[2*ki+1][0] - mn0, s[2*ki+1][1] - mn0));
            pf[ki][3] = h2ex2(packh2(s[2*ki+1][2] - mn1, s[2*ki+1][3] - mn1));
        }

        // exact full-row sums of p via mma against ones (fp32 accumulate)
        float rsac[4] = {0.f, 0.f, 0.f, 0.f};
        #pragma unroll
        for (int ki = 0; ki < 4; ki++)
            mma16816(rsac, pf[ki], ONES2, ONES2);
        l0_ = l0_ * al0 + rsac[0];
        l1_ = l1_ * al1 + rsac[2];

        #pragma unroll
        for (int df = 0; df < 8; df++) {
            o[df][0] *= al0; o[df][1] *= al0;
            o[df][2] *= al1; o[df][3] *= al1;
        }

        // O += P V   (V via ldmatrix.trans on [j][d])
        #pragma unroll
        for (int ki = 0; ki < 4; ki++) {
            uint32_t vb[8][2];
            #pragma unroll
            for (int p = 0; p < 4; p++) {
                int r = ki * 16 + arow;
                LDSM4T(vb[2*p][0], vb[2*p][1], vb[2*p+1][0], vb[2*p+1][1],
                       Vbase + r * 128 + (((p * 2 + acb) ^ (r & 7)) * 16));
            }
            #pragma unroll
            for (int df = 0; df < 8; df++)
                mma16816(o[df], pf[ki], vb[df][0], vb[df][1]);
        }
    }

    // epilogue: l already full-row (ones-mma), normalize, write half
    const float inv0 = 1.f / l0_, inv1 = 1.f / l1_;
    const int b_ = bh >> 4, h_ = bh & 15;
    const int r0 = qs0 + w * 16 + g;
    #pragma unroll
    for (int df = 0; df < 8; df++) {
        int col = h_ * 64 + df * 8 + t2;
        *(__half2*)(g_attnh + (size_t)(b_ * Sn + r0) * Cn + col) =
            __floats2half2_rn(o[df][0] * inv0, o[df][1] * inv0);
        *(__half2*)(g_attnh + (size_t)(b_ * Sn + r0 + 8) * Cn + col) =
            __floats2half2_rn(o[df][2] * inv1, o[df][3] * inv1);
    }
}

// ---------------------------------------------------------------------------
extern "C" void kernel_launch(void* const* d_in, const int* in_sizes, int n_in,
                              void* d_out, int out_size)
{
    (void)in_sizes; (void)n_in; (void)out_size;
    const float* x  = (const float*)d_in[0];
    const float* Wq = (const float*)d_in[1];
    const float* Wk = (const float*)d_in[2];
    const float* Wv = (const float*)d_in[3];
    const float* Wo = (const float*)d_in[4];
    const float* bo = (const float*)d_in[5];
    float* out = (float*)d_out;

    cudaFuncSetAttribute(gemm_h<0>, cudaFuncAttributeMaxDynamicSharedMemorySize, GEMM_SMEM);
    cudaFuncSetAttribute(gemm_h<1>, cudaFuncAttributeMaxDynamicSharedMemorySize, GEMM_SMEM);
    cudaFuncSetAttribute(flash_h,   cudaFuncAttributeMaxDynamicSharedMemorySize, FLASH_SMEM);

    convert_x<<<Mrows * Cn / (256 * 8), 256>>>(x);
    transpose_cvt<<<dim3(2, 32, 16), dim3(32, 8)>>>(Wq, 0, Cn, Dh);
    transpose_cvt<<<dim3(2, 32, 16), dim3(32, 8)>>>(Wk, 1, Cn, Dh);
    transpose_cvt<<<dim3(2, 32, 16), dim3(32, 8)>>>(Wv, 2, Cn, Dh);
    transpose_cvt<<<dim3(32, 32, 1), dim3(32, 8)>>>(Wo, 3, Cn, Cn);

    gemm_h<0><<<dim3(Cn / 128, Mrows / 128, 3), 256, GEMM_SMEM>>>(nullptr, nullptr);
    flash_h<<<dim3(Sn / 128, Bn * Hh), 256, FLASH_SMEM>>>();
    gemm_h<1><<<dim3(Cn / 128, Mrows / 128, 1), 256, GEMM_SMEM>>>(bo, out);
}

// round 7
// speedup vs baseline: 1.0593x; 1.0076x over previous
#include <cuda_runtime.h>
#include <cuda_fp16.h>
#include <cstdint>
#include <math.h>

#define Hh   16
#define Dh   64
#define Bn   2
#define Sn   2048
#define Cn   1024
#define Mrows (Bn*Sn)          // 4096

// ---------------- scratch (__device__ globals; no allocation) --------------
__device__ __half g_xh  [(size_t)Mrows*Cn];
__device__ __half g_wqT [(size_t)Cn*Cn];
__device__ __half g_wkT [(size_t)Cn*Cn];
__device__ __half g_wvT [(size_t)Cn*Cn];
__device__ __half g_woT [(size_t)Cn*Cn];
__device__ __half g_qh  [(size_t)Bn*Hh*Sn*Dh];
__device__ __half g_kh  [(size_t)Bn*Hh*Sn*Dh];
__device__ __half g_vh  [(size_t)Bn*Hh*Sn*Dh];
__device__ __half g_attnh[(size_t)Mrows*Cn];

// ---------------- PTX helpers (base-arch sm_80/sm_75 level only) -----------
__device__ __forceinline__ uint32_t smem_u32(const void* p) {
    uint32_t a;
    asm("{ .reg .u64 t; cvta.to.shared.u64 t, %1; cvt.u32.u64 %0, t; }"
        : "=r"(a) : "l"(p));
    return a;
}
#define CP16(dst, src) \
    asm volatile("cp.async.cg.shared.global [%0], [%1], 16;" :: "r"(dst), "l"(src))
#define CPCOMMIT() asm volatile("cp.async.commit_group;" ::: "memory")
template<int N> __device__ __forceinline__ void cpwait() {
    asm volatile("cp.async.wait_group %0;" :: "n"(N) : "memory");
}
#define LDSM4(d0,d1,d2,d3,addr) \
    asm volatile("ldmatrix.sync.aligned.m8n8.x4.shared.b16 {%0,%1,%2,%3}, [%4];" \
        : "=r"(d0),"=r"(d1),"=r"(d2),"=r"(d3) : "r"(addr))
#define LDSM4T(d0,d1,d2,d3,addr) \
    asm volatile("ldmatrix.sync.aligned.m8n8.x4.trans.shared.b16 {%0,%1,%2,%3}, [%4];" \
        : "=r"(d0),"=r"(d1),"=r"(d2),"=r"(d3) : "r"(addr))

__device__ __forceinline__ void mma16816(float c[4], const uint32_t a[4],
                                         uint32_t b0, uint32_t b1) {
    asm volatile(
        "mma.sync.aligned.m16n8k16.row.col.f32.f16.f16.f32 "
        "{%0,%1,%2,%3},{%4,%5,%6,%7},{%8,%9},{%0,%1,%2,%3};"
        : "+f"(c[0]), "+f"(c[1]), "+f"(c[2]), "+f"(c[3])
        : "r"(a[0]), "r"(a[1]), "r"(a[2]), "r"(a[3]), "r"(b0), "r"(b1));
}
__device__ __forceinline__ uint32_t packh2(float lo, float hi) {
    __half2 h = __floats2half2_rn(lo, hi);
    return *reinterpret_cast<uint32_t*>(&h);
}
__device__ __forceinline__ float ex2f(float x) {
    float y; asm("ex2.approx.f32 %0, %1;" : "=f"(y) : "f"(x)); return y;
}
__device__ __forceinline__ uint32_t h2ex2(uint32_t x) {
    uint32_t y; asm("ex2.approx.f16x2 %0, %1;" : "=r"(y) : "r"(x)); return y;
}

// ---------------------------------------------------------------------------
// convert kernels
// ---------------------------------------------------------------------------
__global__ __launch_bounds__(256) void convert_x(const float* __restrict__ x) {
    size_t i = ((size_t)blockIdx.x * 256 + threadIdx.x) * 8;
    float4 v0 = *(const float4*)(x + i);
    float4 v1 = *(const float4*)(x + i + 4);
    uint4 o;
    o.x = packh2(v0.x, v0.y); o.y = packh2(v0.z, v0.w);
    o.z = packh2(v1.x, v1.y); o.w = packh2(v1.z, v1.w);
    *(uint4*)(&g_xh[i]) = o;
}

// transpose fp32 [R][C] -> half [C][R];  grid.z batches (stride R*C both sides)
__global__ __launch_bounds__(256) void transpose_cvt(const float* __restrict__ in,
                                                     int which, int R, int C) {
    __half* out = (which == 0) ? g_wqT : (which == 1) ? g_wkT
                 : (which == 2) ? g_wvT : g_woT;
    in  += (size_t)blockIdx.z * R * C;
    out += (size_t)blockIdx.z * R * C;
    __shared__ float t[32][33];
    int c0 = blockIdx.x * 32, r0 = blockIdx.y * 32;
    int tx = threadIdx.x, ty = threadIdx.y;
    #pragma unroll
    for (int i = 0; i < 4; i++)
        t[ty + 8*i][tx] = in[(size_t)(r0 + ty + 8*i) * C + c0 + tx];
    __syncthreads();
    #pragma unroll
    for (int i = 0; i < 4; i++)
        out[(size_t)(c0 + ty + 8*i) * R + r0 + tx] = __float2half(t[tx][ty + 8*i]);
}

// ---------------------------------------------------------------------------
// HMMA GEMM: C[M=4096][N=1024] = A[M][K=1024] * B[N][K]^T  (half in, f32 acc)
// 128x128 block tile, BK=64 (128B rows, chunk^row&7 swizzle), 8 warps (2x4),
// warp tile 64x32, 3-stage cp.async pipeline, one __syncthreads per K-step.
// MODE 0: A=g_xh, B=W{q,k,v}T by blockIdx.z, out -> g_{q,k,v}h [b,h,s,d]
//         (q epilogue folds 0.125*log2e so flash works in log2 domain)
// MODE 1: A=g_attnh, B=g_woT, out -> f32 + bias
// ---------------------------------------------------------------------------
#define GSTAGES 3
#define GEMM_SMEM (GSTAGES * 32768)   // 96 KB

template<int MODE>
__global__ __launch_bounds__(256) void gemm_h(const float* __restrict__ bo,
                                              float* __restrict__ outf)
{
    extern __shared__ __align__(16) char sm[];
    const uint32_t sb = smem_u32(sm);
    const int tid = threadIdx.x;
    const int m0 = blockIdx.y * 128, n0 = blockIdx.x * 128;
    const int z = MODE ? 0 : blockIdx.z;
    const __half* A = MODE ? g_attnh : g_xh;
    const __half* B = MODE ? g_woT : (z == 0 ? g_wqT : (z == 1 ? g_wkT : g_wvT));

    float acc[4][4][4];
    #pragma unroll
    for (int i = 0; i < 4; i++)
        #pragma unroll
        for (int j = 0; j < 4; j++)
            #pragma unroll
            for (int r = 0; r < 4; r++) acc[i][j][r] = 0.f;

    const int l = tid & 31, w = tid >> 5, wm = w >> 2, wn = w & 3;
    const int arow_b = wm * 64 + (l & 7) + 8 * ((l >> 3) & 1);
    const int acb = l >> 4;
    const int brow_b = wn * 32 + (l & 7) + 8 * (l >> 4);
    const int bcb = (l >> 3) & 1;

    auto load = [&](int buf, int k0) {
        #pragma unroll
        for (int t = 0; t < 4; t++) {
            int idx = tid + t * 256;
            int row = idx >> 3, c = idx & 7;
            uint32_t sw = (uint32_t)((c ^ (row & 7)) * 16);
            CP16(sb + buf * 16384 + row * 128 + sw,
                 A + (size_t)(m0 + row) * Cn + k0 + c * 8);
            CP16(sb + GSTAGES * 16384 + buf * 16384 + row * 128 + sw,
                 B + (size_t)(n0 + row) * Cn + k0 + c * 8);
        }
    };

    load(0, 0);  CPCOMMIT();
    load(1, 64); CPCOMMIT();

    for (int it = 0; it < 16; it++) {
        cpwait<1>();
        __syncthreads();
        if (it + 2 < 16) load((it + 2) % GSTAGES, (it + 2) * 64);
        CPCOMMIT();

        const int buf = it % GSTAGES;
        const uint32_t Ab = sb + buf * 16384;
        const uint32_t Bb = sb + GSTAGES * 16384 + buf * 16384;
        #pragma unroll
        for (int ks = 0; ks < 4; ks++) {
            uint32_t a[4][4], bf[4][2];
            #pragma unroll
            for (int mf = 0; mf < 4; mf++) {
                int r = arow_b + mf * 16;
                LDSM4(a[mf][0], a[mf][1], a[mf][2], a[mf][3],
                      Ab + r * 128 + (((ks * 2 + acb) ^ (r & 7)) * 16));
            }
            #pragma unroll
            for (int p = 0; p < 2; p++) {
                int r = brow_b + p * 16;
                LDSM4(bf[2*p][0], bf[2*p][1], bf[2*p+1][0], bf[2*p+1][1],
                      Bb + r * 128 + (((ks * 2 + bcb) ^ (r & 7)) * 16));
            }
            #pragma unroll
            for (int mf = 0; mf < 4; mf++)
                #pragma unroll
                for (int nf = 0; nf < 4; nf++)
                    mma16816(acc[mf][nf], a[mf], bf[nf][0], bf[nf][1]);
        }
    }

    // epilogue
    const int g = l >> 2, t2 = (l & 3) * 2;
    if (MODE == 0) {
        // q scale: 1/sqrt(D) * log2(e)  (flash softmax runs in log2 domain)
        const float sc = (z == 0) ? 0.180336881f : 1.0f;
        __half* O = (z == 0) ? g_qh : (z == 1) ? g_kh : g_vh;
        #pragma unroll
        for (int mf = 0; mf < 4; mf++) {
            int row = m0 + wm * 64 + mf * 16 + g;
            int b_ = row >> 11, s = row & (Sn - 1);
            #pragma unroll
            for (int nf = 0; nf < 4; nf++) {
                int col = n0 + wn * 32 + nf * 8 + t2;
                int h = col >> 6, d = col & 63;
                size_t i0 = (((size_t)b_ * Hh + h) * Sn + s) * Dh + d;
                *(__half2*)(O + i0) =
                    __floats2half2_rn(acc[mf][nf][0] * sc, acc[mf][nf][1] * sc);
                *(__half2*)(O + i0 + 8 * Dh) =
                    __floats2half2_rn(acc[mf][nf][2] * sc, acc[mf][nf][3] * sc);
            }
        }
    } else {
        #pragma unroll
        for (int mf = 0; mf < 4; mf++) {
            int row = m0 + wm * 64 + mf * 16 + g;
            #pragma unroll
            for (int nf = 0; nf < 4; nf++) {
                int col = n0 + wn * 32 + nf * 8 + t2;
                float b0v = bo[col], b1v = bo[col + 1];
                *(float2*)(outf + (size_t)row * Cn + col) =
                    make_float2(acc[mf][nf][0] + b0v, acc[mf][nf][1] + b1v);
                *(float2*)(outf + (size_t)(row + 8) * Cn + col) =
                    make_float2(acc[mf][nf][2] + b0v, acc[mf][nf][3] + b1v);
            }
        }
    }
}

// ---------------------------------------------------------------------------
// HMMA causal flash attention, log2-domain softmax.
// Br=128, Bc=64, D=64.  8 warps, warp owns a 16-row strip.
// p = ex2.approx.f16x2 (packed halves feed the P*V A-fragments directly),
// row sums via an extra mma against a ones B-fragment (exact fp32, full-row).
// 3-stage cp.async KV pipeline; heavy CTAs (large qt) launch first.
// ---------------------------------------------------------------------------
#define FSTAGES 3
#define FLASH_SMEM (16384 + FSTAGES * 16384)   // Q + 3 KV stages = 64 KB

__global__ __launch_bounds__(256) void flash_h()
{
    extern __shared__ __align__(16) char sm[];
    const uint32_t sb = smem_u32(sm);
    const int tid = threadIdx.x;
    const int l = tid & 31, w = tid >> 5;
    const int bh = blockIdx.y;
    const int qt = gridDim.x - 1 - blockIdx.x;   // heavy tiles first
    const int qs0 = qt * 128;

    const __half* Qb = g_qh + (size_t)bh * Sn * Dh;
    const __half* Kb = g_kh + (size_t)bh * Sn * Dh;
    const __half* Vb = g_vh + (size_t)bh * Sn * Dh;

    auto load_kv = [&](int buf, int ks0) {
        #pragma unroll
        for (int t = 0; t < 4; t++) {
            int idx = tid + t * 256;
            int which = idx >> 9;            // 0=K, 1=V
            int r = (idx >> 3) & 63, c = idx & 7;
            const __half* src = (which ? Vb : Kb) + (size_t)(ks0 + r) * Dh + c * 8;
            uint32_t dst = sb + 16384 + buf * 16384 + which * 8192
                         + r * 128 + ((c ^ (r & 7)) * 16);
            CP16(dst, src);
        }
    };

    const int nt = 2 * qt + 2;

    // prologue: Q + KV(0) in group 0, KV(1) in group 1
    #pragma unroll
    for (int t = 0; t < 4; t++) {
        int idx = tid + t * 256;
        int row = idx >> 3, c = idx & 7;
        CP16(sb + row * 128 + ((c ^ (row & 7)) * 16),
             Qb + (size_t)(qs0 + row) * Dh + c * 8);
    }
    load_kv(0, 0);
    CPCOMMIT();
    load_kv(1, 64);   // nt >= 2 always
    CPCOMMIT();

    uint32_t qf[4][4];
    float o[8][4];
    #pragma unroll
    for (int i = 0; i < 8; i++)
        #pragma unroll
        for (int j = 0; j < 4; j++) o[i][j] = 0.f;
    float m0_ = -1e30f, m1_ = -1e30f, l0_ = 0.f, l1_ = 0.f;

    const int g = l >> 2, t2 = (l & 3) * 2;
    const int arow = (l & 7) + 8 * ((l >> 3) & 1);  // Q / V row pattern
    const int acb  = l >> 4;
    const int brow = (l & 7) + 8 * (l >> 4);        // K row pattern
    const int bcb  = (l >> 3) & 1;
    const uint32_t ONES2 = 0x3C003C00u;             // half2(1,1)

    for (int jt = 0; jt < nt; jt++) {
        cpwait<1>();
        __syncthreads();
        if (jt + 2 < nt) load_kv((jt + 2) % FSTAGES, (jt + 2) * 64);
        CPCOMMIT();

        if (jt == 0) {
            #pragma unroll
            for (int ks = 0; ks < 4; ks++) {
                int r = w * 16 + arow;
                LDSM4(qf[ks][0], qf[ks][1], qf[ks][2], qf[ks][3],
                      sb + r * 128 + (((ks * 2 + acb) ^ (r & 7)) * 16));
            }
        }
        const int buf = jt % FSTAGES;
        const uint32_t Kbase = sb + 16384 + buf * 16384;
        const uint32_t Vbase = Kbase + 8192;

        // S = Q K^T  (16 x 64 per warp), already in log2 domain
        float s[8][4];
        #pragma unroll
        for (int i = 0; i < 8; i++)
            #pragma unroll
            for (int j = 0; j < 4; j++) s[i][j] = 0.f;
        #pragma unroll
        for (int ks = 0; ks < 4; ks++) {
            uint32_t kb[8][2];
            #pragma unroll
            for (int p = 0; p < 4; p++) {
                int r = p * 16 + brow;
                LDSM4(kb[2*p][0], kb[2*p][1], kb[2*p+1][0], kb[2*p+1][1],
                      Kbase + r * 128 + (((ks * 2 + bcb) ^ (r & 7)) * 16));
            }
            #pragma unroll
            for (int nf = 0; nf < 8; nf++)
                mma16816(s[nf], qf[ks], kb[nf][0], kb[nf][1]);
        }

        // causal mask (diag tiles only)
        const int ks0 = jt * 64;
        const int rg = qs0 + w * 16 + g;
        if (jt >= nt - 2) {
            #pragma unroll
            for (int nf = 0; nf < 8; nf++) {
                int c0 = ks0 + nf * 8 + t2;
                if (c0     > rg    ) s[nf][0] = -1e30f;
                if (c0 + 1 > rg    ) s[nf][1] = -1e30f;
                if (c0     > rg + 8) s[nf][2] = -1e30f;
                if (c0 + 1 > rg + 8) s[nf][3] = -1e30f;
            }
        }

        // online softmax (rows g and g+8), log2 domain
        float x0 = -1e30f, x1 = -1e30f;
        #pragma unroll
        for (int nf = 0; nf < 8; nf++) {
            x0 = fmaxf(x0, fmaxf(s[nf][0], s[nf][1]));
            x1 = fmaxf(x1, fmaxf(s[nf][2], s[nf][3]));
        }
        x0 = fmaxf(x0, __shfl_xor_sync(0xffffffffu, x0, 1));
        x0 = fmaxf(x0, __shfl_xor_sync(0xffffffffu, x0, 2));
        x1 = fmaxf(x1, __shfl_xor_sync(0xffffffffu, x1, 1));
        x1 = fmaxf(x1, __shfl_xor_sync(0xffffffffu, x1, 2));
        float mn0 = fmaxf(m0_, x0), mn1 = fmaxf(m1_, x1);
        float al0 = ex2f(m0_ - mn0), al1 = ex2f(m1_ - mn1);
        m0_ = mn0; m1_ = mn1;

        // p = 2^(s - m) as packed half2 == A fragments of P*V
        uint32_t pf[4][4];
        #pragma unroll
        for (int ki = 0; ki < 4; ki++) {
            pf[ki][0] = h2ex2(packh2(s[2*ki][0]   - mn0, s[2*ki][1]   - mn0));
            pf[ki][1] = h2ex2(packh2(s[2*ki][2]   - mn1, s[2*ki][3]   - mn1));
            pf[ki][2] = h2ex2(packh2(s[2*ki+1][0] - mn0, s[2*ki+1][1] - mn0));
            pf[ki][3] = h2ex2(packh2(s[2*ki+1][2] - mn1, s[2*ki+1][3] - mn1));
        }

        // exact full-row sums of p via mma against ones (fp32 accumulate)
        float rsac[4] = {0.f, 0.f, 0.f, 0.f};
        #pragma unroll
        for (int ki = 0; ki < 4; ki++)
            mma16816(rsac, pf[ki], ONES2, ONES2);
        l0_ = l0_ * al0 + rsac[0];
        l1_ = l1_ * al1 + rsac[2];

        #pragma unroll
        for (int df = 0; df < 8; df++) {
            o[df][0] *= al0; o[df][1] *= al0;
            o[df][2] *= al1; o[df][3] *= al1;
        }

        // O += P V   (V via ldmatrix.trans on [j][d])
        #pragma unroll
        for (int ki = 0; ki < 4; ki++) {
            uint32_t vb[8][2];
            #pragma unroll
            for (int p = 0; p < 4; p++) {
                int r = ki * 16 + arow;
                LDSM4T(vb[2*p][0], vb[2*p][1], vb[2*p+1][0], vb[2*p+1][1],
                       Vbase + r * 128 + (((p * 2 + acb) ^ (r & 7)) * 16));
            }
            #pragma unroll
            for (int df = 0; df < 8; df++)
                mma16816(o[df], pf[ki], vb[df][0], vb[df][1]);
        }
    }

    // epilogue: l already full-row (ones-mma), normalize, write half
    const float inv0 = 1.f / l0_, inv1 = 1.f / l1_;
    const int b_ = bh >> 4, h_ = bh & 15;
    const int r0 = qs0 + w * 16 + g;
    #pragma unroll
    for (int df = 0; df < 8; df++) {
        int col = h_ * 64 + df * 8 + t2;
        *(__half2*)(g_attnh + (size_t)(b_ * Sn + r0) * Cn + col) =
            __floats2half2_rn(o[df][0] * inv0, o[df][1] * inv0);
        *(__half2*)(g_attnh + (size_t)(b_ * Sn + r0 + 8) * Cn + col) =
            __floats2half2_rn(o[df][2] * inv1, o[df][3] * inv1);
    }
}

// ---------------------------------------------------------------------------
extern "C" void kernel_launch(void* const* d_in, const int* in_sizes, int n_in,
                              void* d_out, int out_size)
{
    (void)in_sizes; (void)n_in; (void)out_size;
    const float* x  = (const float*)d_in[0];
    const float* Wq = (const float*)d_in[1];
    const float* Wk = (const float*)d_in[2];
    const float* Wv = (const float*)d_in[3];
    const float* Wo = (const float*)d_in[4];
    const float* bo = (const float*)d_in[5];
    float* out = (float*)d_out;

    cudaFuncSetAttribute(gemm_h<0>, cudaFuncAttributeMaxDynamicSharedMemorySize, GEMM_SMEM);
    cudaFuncSetAttribute(gemm_h<1>, cudaFuncAttributeMaxDynamicSharedMemorySize, GEMM_SMEM);
    cudaFuncSetAttribute(flash_h,   cudaFuncAttributeMaxDynamicSharedMemorySize, FLASH_SMEM);

    convert_x<<<Mrows * Cn / (256 * 8), 256>>>(x);
    transpose_cvt<<<dim3(2, 32, 16), dim3(32, 8)>>>(Wq, 0, Cn, Dh);
    transpose_cvt<<<dim3(2, 32, 16), dim3(32, 8)>>>(Wk, 1, Cn, Dh);
    transpose_cvt<<<dim3(2, 32, 16), dim3(32, 8)>>>(Wv, 2, Cn, Dh);
    transpose_cvt<<<dim3(32, 32, 1), dim3(32, 8)>>>(Wo, 3, Cn, Cn);

    gemm_h<0><<<dim3(Cn / 128, Mrows / 128, 3), 256, GEMM_SMEM>>>(nullptr, nullptr);
    flash_h<<<dim3(Sn / 128, Bn * Hh), 256, FLASH_SMEM>>>();
    gemm_h<1><<<dim3(Cn / 128, Mrows / 128, 1), 256, GEMM_SMEM>>>(bo, out);
}

// round 8
// speedup vs baseline: 1.0615x; 1.0021x over previous
#include <cuda_runtime.h>
#include <cuda_fp16.h>
#include <cstdint>
#include <math.h>

#define Hh   16
#define Dh   64
#define Bn   2
#define Sn   2048
#define Cn   1024
#define Mrows (Bn*Sn)          // 4096

// ---------------- scratch (__device__ globals; no allocation) --------------
__device__ __half g_xh  [(size_t)Mrows*Cn];
__device__ __half g_wqT [(size_t)Cn*Cn];
__device__ __half g_wkT [(size_t)Cn*Cn];
__device__ __half g_wvT [(size_t)Cn*Cn];
__device__ __half g_woT [(size_t)Cn*Cn];
__device__ __half g_qh  [(size_t)Bn*Hh*Sn*Dh];
__device__ __half g_kh  [(size_t)Bn*Hh*Sn*Dh];
__device__ __half g_vh  [(size_t)Bn*Hh*Sn*Dh];
__device__ __half g_attnh[(size_t)Mrows*Cn];

// ---------------- PTX helpers (base-arch sm_80/sm_75 level only) -----------
__device__ __forceinline__ uint32_t smem_u32(const void* p) {
    uint32_t a;
    asm("{ .reg .u64 t; cvta.to.shared.u64 t, %1; cvt.u32.u64 %0, t; }"
        : "=r"(a) : "l"(p));
    return a;
}
#define CP16(dst, src) \
    asm volatile("cp.async.cg.shared.global [%0], [%1], 16;" :: "r"(dst), "l"(src))
#define CPCOMMIT() asm volatile("cp.async.commit_group;" ::: "memory")
template<int N> __device__ __forceinline__ void cpwait() {
    asm volatile("cp.async.wait_group %0;" :: "n"(N) : "memory");
}
#define LDSM4(d0,d1,d2,d3,addr) \
    asm volatile("ldmatrix.sync.aligned.m8n8.x4.shared.b16 {%0,%1,%2,%3}, [%4];" \
        : "=r"(d0),"=r"(d1),"=r"(d2),"=r"(d3) : "r"(addr))
#define LDSM4T(d0,d1,d2,d3,addr) \
    asm volatile("ldmatrix.sync.aligned.m8n8.x4.trans.shared.b16 {%0,%1,%2,%3}, [%4];" \
        : "=r"(d0),"=r"(d1),"=r"(d2),"=r"(d3) : "r"(addr))

__device__ __forceinline__ void mma16816(float c[4], const uint32_t a[4],
                                         uint32_t b0, uint32_t b1) {
    asm volatile(
        "mma.sync.aligned.m16n8k16.row.col.f32.f16.f16.f32 "
        "{%0,%1,%2,%3},{%4,%5,%6,%7},{%8,%9},{%0,%1,%2,%3};"
        : "+f"(c[0]), "+f"(c[1]), "+f"(c[2]), "+f"(c[3])
        : "r"(a[0]), "r"(a[1]), "r"(a[2]), "r"(a[3]), "r"(b0), "r"(b1));
}
__device__ __forceinline__ uint32_t packh2(float lo, float hi) {
    __half2 h = __floats2half2_rn(lo, hi);
    return *reinterpret_cast<uint32_t*>(&h);
}
__device__ __forceinline__ float ex2f(float x) {
    float y; asm("ex2.approx.f32 %0, %1;" : "=f"(y) : "f"(x)); return y;
}
__device__ __forceinline__ uint32_t h2ex2(uint32_t x) {
    uint32_t y; asm("ex2.approx.f16x2 %0, %1;" : "=r"(y) : "r"(x)); return y;
}

// ---------------------------------------------------------------------------
// convert kernels
// ---------------------------------------------------------------------------
__global__ __launch_bounds__(256) void convert_x(const float* __restrict__ x) {
    size_t i = ((size_t)blockIdx.x * 256 + threadIdx.x) * 8;
    float4 v0 = *(const float4*)(x + i);
    float4 v1 = *(const float4*)(x + i + 4);
    uint4 o;
    o.x = packh2(v0.x, v0.y); o.y = packh2(v0.z, v0.w);
    o.z = packh2(v1.x, v1.y); o.w = packh2(v1.z, v1.w);
    *(uint4*)(&g_xh[i]) = o;
}

// transpose fp32 [R][C] -> half [C][R];  grid.z batches (stride R*C both sides)
__global__ __launch_bounds__(256) void transpose_cvt(const float* __restrict__ in,
                                                     int which, int R, int C) {
    __half* out = (which == 0) ? g_wqT : (which == 1) ? g_wkT
                 : (which == 2) ? g_wvT : g_woT;
    in  += (size_t)blockIdx.z * R * C;
    out += (size_t)blockIdx.z * R * C;
    __shared__ float t[32][33];
    int c0 = blockIdx.x * 32, r0 = blockIdx.y * 32;
    int tx = threadIdx.x, ty = threadIdx.y;
    #pragma unroll
    for (int i = 0; i < 4; i++)
        t[ty + 8*i][tx] = in[(size_t)(r0 + ty + 8*i) * C + c0 + tx];
    __syncthreads();
    #pragma unroll
    for (int i = 0; i < 4; i++)
        out[(size_t)(c0 + ty + 8*i) * R + r0 + tx] = __float2half(t[tx][ty + 8*i]);
}

// ---------------------------------------------------------------------------
// HMMA GEMM: C[M=4096][N=1024] = A[M][K=1024] * B[N][K]^T  (half in, f32 acc)
// 128x128 block tile, BK=64 (128B rows, chunk^row&7 swizzle), 8 warps (2x4),
// warp tile 64x32, 3-stage cp.async pipeline, one __syncthreads per K-step.
// MODE 0: A=g_xh, B=W{q,k,v}T by blockIdx.z, out -> g_{q,k,v}h [b,h,s,d]
//         (q epilogue folds 0.125*log2e so flash works in log2 domain)
// MODE 1: A=g_attnh, B=g_woT, out -> f32 + bias
// ---------------------------------------------------------------------------
#define GSTAGES 3
#define GEMM_SMEM (GSTAGES * 32768)   // 96 KB

template<int MODE>
__global__ __launch_bounds__(256) void gemm_h(const float* __restrict__ bo,
                                              float* __restrict__ outf)
{
    extern __shared__ __align__(16) char sm[];
    const uint32_t sb = smem_u32(sm);
    const int tid = threadIdx.x;
    const int m0 = blockIdx.y * 128, n0 = blockIdx.x * 128;
    const int z = MODE ? 0 : blockIdx.z;
    const __half* A = MODE ? g_attnh : g_xh;
    const __half* B = MODE ? g_woT : (z == 0 ? g_wqT : (z == 1 ? g_wkT : g_wvT));

    float acc[4][4][4];
    #pragma unroll
    for (int i = 0; i < 4; i++)
        #pragma unroll
        for (int j = 0; j < 4; j++)
            #pragma unroll
            for (int r = 0; r < 4; r++) acc[i][j][r] = 0.f;

    const int l = tid & 31, w = tid >> 5, wm = w >> 2, wn = w & 3;
    const int arow_b = wm * 64 + (l & 7) + 8 * ((l >> 3) & 1);
    const int acb = l >> 4;
    const int brow_b = wn * 32 + (l & 7) + 8 * (l >> 4);
    const int bcb = (l >> 3) & 1;

    auto load = [&](int buf, int k0) {
        #pragma unroll
        for (int t = 0; t < 4; t++) {
            int idx = tid + t * 256;
            int row = idx >> 3, c = idx & 7;
            uint32_t sw = (uint32_t)((c ^ (row & 7)) * 16);
            CP16(sb + buf * 16384 + row * 128 + sw,
                 A + (size_t)(m0 + row) * Cn + k0 + c * 8);
            CP16(sb + GSTAGES * 16384 + buf * 16384 + row * 128 + sw,
                 B + (size_t)(n0 + row) * Cn + k0 + c * 8);
        }
    };

    load(0, 0);  CPCOMMIT();
    load(1, 64); CPCOMMIT();

    for (int it = 0; it < 16; it++) {
        cpwait<1>();
        __syncthreads();
        if (it + 2 < 16) load((it + 2) % GSTAGES, (it + 2) * 64);
        CPCOMMIT();

        const int buf = it % GSTAGES;
        const uint32_t Ab = sb + buf * 16384;
        const uint32_t Bb = sb + GSTAGES * 16384 + buf * 16384;
        #pragma unroll
        for (int ks = 0; ks < 4; ks++) {
            uint32_t a[4][4], bf[4][2];
            #pragma unroll
            for (int mf = 0; mf < 4; mf++) {
                int r = arow_b + mf * 16;
                LDSM4(a[mf][0], a[mf][1], a[mf][2], a[mf][3],
                      Ab + r * 128 + (((ks * 2 + acb) ^ (r & 7)) * 16));
            }
            #pragma unroll
            for (int p = 0; p < 2; p++) {
                int r = brow_b + p * 16;
                LDSM4(bf[2*p][0], bf[2*p][1], bf[2*p+1][0], bf[2*p+1][1],
                      Bb + r * 128 + (((ks * 2 + bcb) ^ (r & 7)) * 16));
            }
            #pragma unroll
            for (int mf = 0; mf < 4; mf++)
                #pragma unroll
                for (int nf = 0; nf < 4; nf++)
                    mma16816(acc[mf][nf], a[mf], bf[nf][0], bf[nf][1]);
        }
    }

    // epilogue
    const int g = l >> 2, t2 = (l & 3) * 2;
    if (MODE == 0) {
        // q scale: 1/sqrt(D) * log2(e)  (flash softmax runs in log2 domain)
        const float sc = (z == 0) ? 0.180336881f : 1.0f;
        __half* O = (z == 0) ? g_qh : (z == 1) ? g_kh : g_vh;
        #pragma unroll
        for (int mf = 0; mf < 4; mf++) {
            int row = m0 + wm * 64 + mf * 16 + g;
            int b_ = row >> 11, s = row & (Sn - 1);
            #pragma unroll
            for (int nf = 0; nf < 4; nf++) {
                int col = n0 + wn * 32 + nf * 8 + t2;
                int h = col >> 6, d = col & 63;
                size_t i0 = (((size_t)b_ * Hh + h) * Sn + s) * Dh + d;
                *(__half2*)(O + i0) =
                    __floats2half2_rn(acc[mf][nf][0] * sc, acc[mf][nf][1] * sc);
                *(__half2*)(O + i0 + 8 * Dh) =
                    __floats2half2_rn(acc[mf][nf][2] * sc, acc[mf][nf][3] * sc);
            }
        }
    } else {
        #pragma unroll
        for (int mf = 0; mf < 4; mf++) {
            int row = m0 + wm * 64 + mf * 16 + g;
            #pragma unroll
            for (int nf = 0; nf < 4; nf++) {
                int col = n0 + wn * 32 + nf * 8 + t2;
                float b0v = bo[col], b1v = bo[col + 1];
                *(float2*)(outf + (size_t)row * Cn + col) =
                    make_float2(acc[mf][nf][0] + b0v, acc[mf][nf][1] + b1v);
                *(float2*)(outf + (size_t)(row + 8) * Cn + col) =
                    make_float2(acc[mf][nf][2] + b0v, acc[mf][nf][3] + b1v);
            }
        }
    }
}

// ---------------------------------------------------------------------------
// HMMA causal flash attention, log2-domain softmax.
// Br=128, Bc=64, D=64.  8 warps, warp owns a 16-row strip.
// p = ex2.approx.f16x2 (packed halves feed the P*V A-fragments directly),
// row sums via an extra mma against a ones B-fragment (exact fp32, full-row).
// 3-stage cp.async KV pipeline; heavy CTAs (large qt) launch first.
// ---------------------------------------------------------------------------
#define FSTAGES 3
#define FLASH_SMEM (16384 + FSTAGES * 16384)   // Q + 3 KV stages = 64 KB

__global__ __launch_bounds__(256) void flash_h()
{
    extern __shared__ __align__(16) char sm[];
    const uint32_t sb = smem_u32(sm);
    const int tid = threadIdx.x;
    const int l = tid & 31, w = tid >> 5;
    const int bh = blockIdx.y;
    const int qt = gridDim.x - 1 - blockIdx.x;   // heavy tiles first
    const int qs0 = qt * 128;

    const __half* Qb = g_qh + (size_t)bh * Sn * Dh;
    const __half* Kb = g_kh + (size_t)bh * Sn * Dh;
    const __half* Vb = g_vh + (size_t)bh * Sn * Dh;

    auto load_kv = [&](int buf, int ks0) {
        #pragma unroll
        for (int t = 0; t < 4; t++) {
            int idx = tid + t * 256;
            int which = idx >> 9;            // 0=K, 1=V
            int r = (idx >> 3) & 63, c = idx & 7;
            const __half* src = (which ? Vb : Kb) + (size_t)(ks0 + r) * Dh + c * 8;
            uint32_t dst = sb + 16384 + buf * 16384 + which * 8192
                         + r * 128 + ((c ^ (r & 7)) * 16);
            CP16(dst, src);
        }
    };

    const int nt = 2 * qt + 2;

    // prologue: Q + KV(0) in group 0, KV(1) in group 1
    #pragma unroll
    for (int t = 0; t < 4; t++) {
        int idx = tid + t * 256;
        int row = idx >> 3, c = idx & 7;
        CP16(sb + row * 128 + ((c ^ (row & 7)) * 16),
             Qb + (size_t)(qs0 + row) * Dh + c * 8);
    }
    load_kv(0, 0);
    CPCOMMIT();
    load_kv(1, 64);   // nt >= 2 always
    CPCOMMIT();

    uint32_t qf[4][4];
    float o[8][4];
    #pragma unroll
    for (int i = 0; i < 8; i++)
        #pragma unroll
        for (int j = 0; j < 4; j++) o[i][j] = 0.f;
    float m0_ = -1e30f, m1_ = -1e30f, l0_ = 0.f, l1_ = 0.f;

    const int g = l >> 2, t2 = (l & 3) * 2;
    const int arow = (l & 7) + 8 * ((l >> 3) & 1);  // Q / V row pattern
    const int acb  = l >> 4;
    const int brow = (l & 7) + 8 * (l >> 4);        // K row pattern
    const int bcb  = (l >> 3) & 1;
    const uint32_t ONES2 = 0x3C003C00u;             // half2(1,1)

    for (int jt = 0; jt < nt; jt++) {
        cpwait<1>();
        __syncthreads();
        if (jt + 2 < nt) load_kv((jt + 2) % FSTAGES, (jt + 2) * 64);
        CPCOMMIT();

        if (jt == 0) {
            #pragma unroll
            for (int ks = 0; ks < 4; ks++) {
                int r = w * 16 + arow;
                LDSM4(qf[ks][0], qf[ks][1], qf[ks][2], qf[ks][3],
                      sb + r * 128 + (((ks * 2 + acb) ^ (r & 7)) * 16));
            }
        }
        const int buf = jt % FSTAGES;
        const uint32_t Kbase = sb + 16384 + buf * 16384;
        const uint32_t Vbase = Kbase + 8192;

        // S = Q K^T  (16 x 64 per warp), already in log2 domain
        float s[8][4];
        #pragma unroll
        for (int i = 0; i < 8; i++)
            #pragma unroll
            for (int j = 0; j < 4; j++) s[i][j] = 0.f;
        #pragma unroll
        for (int ks = 0; ks < 4; ks++) {
            uint32_t kb[8][2];
            #pragma unroll
            for (int p = 0; p < 4; p++) {
                int r = p * 16 + brow;
                LDSM4(kb[2*p][0], kb[2*p][1], kb[2*p+1][0], kb[2*p+1][1],
                      Kbase + r * 128 + (((ks * 2 + bcb) ^ (r & 7)) * 16));
            }
            #pragma unroll
            for (int nf = 0; nf < 8; nf++)
                mma16816(s[nf], qf[ks], kb[nf][0], kb[nf][1]);
        }

        // causal mask (diag tiles only)
        const int ks0 = jt * 64;
        const int rg = qs0 + w * 16 + g;
        if (jt >= nt - 2) {
            #pragma unroll
            for (int nf = 0; nf < 8; nf++) {
                int c0 = ks0 + nf * 8 + t2;
                if (c0     > rg    ) s[nf][0] = -1e30f;
                if (c0 + 1 > rg    ) s[nf][1] = -1e30f;
                if (c0     > rg + 8) s[nf][2] = -1e30f;
                if (c0 + 1 > rg + 8) s[nf][3] = -1e30f;
            }
        }

        // online softmax (rows g and g+8), log2 domain
        float x0 = -1e30f, x1 = -1e30f;
        #pragma unroll
        for (int nf = 0; nf < 8; nf++) {
            x0 = fmaxf(x0, fmaxf(s[nf][0], s[nf][1]));
            x1 = fmaxf(x1, fmaxf(s[nf][2], s[nf][3]));
        }
        x0 = fmaxf(x0, __shfl_xor_sync(0xffffffffu, x0, 1));
        x0 = fmaxf(x0, __shfl_xor_sync(0xffffffffu, x0, 2));
        x1 = fmaxf(x1, __shfl_xor_sync(0xffffffffu, x1, 1));
        x1 = fmaxf(x1, __shfl_xor_sync(0xffffffffu, x1, 2));
        float mn0 = fmaxf(m0_, x0), mn1 = fmaxf(m1_, x1);
        float al0 = ex2f(m0_ - mn0), al1 = ex2f(m1_ - mn1);
        m0_ = mn0; m1_ = mn1;

        // p = 2^(s - m) as packed half2 == A fragments of P*V
        uint32_t pf[4][4];
        #pragma unroll
        for (int ki = 0; ki < 4; ki++) {
            pf[ki][0] = h2ex2(packh2(s[2*ki][0]   - mn0, s[2*ki][1]   - mn0));
            pf[ki][1] = h2ex2(packh2(s[2*ki][2]   - mn1, s[2*ki][3]   - mn1));
            pf[ki][2] = h2ex2(packh2(s[2*ki+1][0] - mn0, s[2*ki+1][1] - mn0));
            pf[ki][3] = h2ex2(packh2(s[2*ki+1][2] - mn1, s[2*ki+1][3] - mn1));
        }

        // exact full-row sums of p via mma against ones (fp32 accumulate)
        float rsac[4] = {0.f, 0.f, 0.f, 0.f};
        #pragma unroll
        for (int ki = 0; ki < 4; ki++)
            mma16816(rsac, pf[ki], ONES2, ONES2);
        l0_ = l0_ * al0 + rsac[0];
        l1_ = l1_ * al1 + rsac[2];

        #pragma unroll
        for (int df = 0; df < 8; df++) {
            o[df][0] *= al0; o[df][1] *= al0;
            o[df][2] *= al1; o[df][3] *= al1;
        }

        // O += P V   (V via ldmatrix.trans on [j][d])
        #pragma unroll
        for (int ki = 0; ki < 4; ki++) {
            uint32_t vb[8][2];
            #pragma unroll
            for (int p = 0; p < 4; p++) {
                int r = ki * 16 + arow;
                LDSM4T(vb[2*p][0], vb[2*p][1], vb[2*p+1][0], vb[2*p+1][1],
                       Vbase + r * 128 + (((p * 2 + acb) ^ (r & 7)) * 16));
            }
            #pragma unroll
            for (int df = 0; df < 8; df++)
                mma16816(o[df], pf[ki], vb[df][0], vb[df][1]);
        }
    }

    // epilogue: l already full-row (ones-mma), normalize, write half
    const float inv0 = 1.f / l0_, inv1 = 1.f / l1_;
    const int b_ = bh >> 4, h_ = bh & 15;
    const int r0 = qs0 + w * 16 + g;
    #pragma unroll
    for (int df = 0; df < 8; df++) {
        int col = h_ * 64 + df * 8 + t2;
        *(__half2*)(g_attnh + (size_t)(b_ * Sn + r0) * Cn + col) =
            __floats2half2_rn(o[df][0] * inv0, o[df][1] * inv0);
        *(__half2*)(g_attnh + (size_t)(b_ * Sn + r0 + 8) * Cn + col) =
            __floats2half2_rn(o[df][2] * inv1, o[df][3] * inv1);
    }
}

// ---------------------------------------------------------------------------
extern "C" void kernel_launch(void* const* d_in, const int* in_sizes, int n_in,
                              void* d_out, int out_size)
{
    (void)in_sizes; (void)n_in; (void)out_size;
    const float* x  = (const float*)d_in[0];
    const float* Wq = (const float*)d_in[1];
    const float* Wk = (const float*)d_in[2];
    const float* Wv = (const float*)d_in[3];
    const float* Wo = (const float*)d_in[4];
    const float* bo = (const float*)d_in[5];
    float* out = (float*)d_out;

    cudaFuncSetAttribute(gemm_h<0>, cudaFuncAttributeMaxDynamicSharedMemorySize, GEMM_SMEM);
    cudaFuncSetAttribute(gemm_h<1>, cudaFuncAttributeMaxDynamicSharedMemorySize, GEMM_SMEM);
    cudaFuncSetAttribute(flash_h,   cudaFuncAttributeMaxDynamicSharedMemorySize, FLASH_SMEM);

    convert_x<<<Mrows * Cn / (256 * 8), 256>>>(x);
    transpose_cvt<<<dim3(2, 32, 16), dim3(32, 8)>>>(Wq, 0, Cn, Dh);
    transpose_cvt<<<dim3(2, 32, 16), dim3(32, 8)>>>(Wk, 1, Cn, Dh);
    transpose_cvt<<<dim3(2, 32, 16), dim3(32, 8)>>>(Wv, 2, Cn, Dh);
    transpose_cvt<<<dim3(32, 32, 1), dim3(32, 8)>>>(Wo, 3, Cn, Cn);

    gemm_h<0><<<dim3(Cn / 128, Mrows / 128, 3), 256, GEMM_SMEM>>>(nullptr, nullptr);
    flash_h<<<dim3(Sn / 128, Bn * Hh), 256, FLASH_SMEM>>>();
    gemm_h<1><<<dim3(Cn / 128, Mrows / 128, 1), 256, GEMM_SMEM>>>(bo, out);
}

// round 9
// speedup vs baseline: 1.1047x; 1.0407x over previous
#include <cuda_runtime.h>
#include <cuda_fp16.h>
#include <cstdint>
#include <math.h>

#define Hh   16
#define Dh   64
#define Bn   2
#define Sn   2048
#define Cn   1024
#define Mrows (Bn*Sn)          // 4096

// ---------------- scratch (__device__ globals; no allocation) --------------
__device__ __half g_xh  [(size_t)Mrows*Cn];
__device__ __half g_wqh [(size_t)Cn*Cn];    // [H][C][D] half (natural layout)
__device__ __half g_wkh [(size_t)Cn*Cn];
__device__ __half g_wvh [(size_t)Cn*Cn];
__device__ __half g_woh [(size_t)Cn*Cn];    // [C][C] half (k-major natural)
__device__ __half g_qh  [(size_t)Bn*Hh*Sn*Dh];
__device__ __half g_kh  [(size_t)Bn*Hh*Sn*Dh];
__device__ __half g_vh  [(size_t)Bn*Hh*Sn*Dh];
__device__ __half g_attnh[(size_t)Mrows*Cn];

// ---------------- PTX helpers (base-arch sm_80/sm_75 level only) -----------
__device__ __forceinline__ uint32_t smem_u32(const void* p) {
    uint32_t a;
    asm("{ .reg .u64 t; cvta.to.shared.u64 t, %1; cvt.u32.u64 %0, t; }"
        : "=r"(a) : "l"(p));
    return a;
}
#define CP16(dst, src) \
    asm volatile("cp.async.cg.shared.global [%0], [%1], 16;" :: "r"(dst), "l"(src))
#define CPCOMMIT() asm volatile("cp.async.commit_group;" ::: "memory")
template<int N> __device__ __forceinline__ void cpwait() {
    asm volatile("cp.async.wait_group %0;" :: "n"(N) : "memory");
}
#define LDSM4(d0,d1,d2,d3,addr) \
    asm volatile("ldmatrix.sync.aligned.m8n8.x4.shared.b16 {%0,%1,%2,%3}, [%4];" \
        : "=r"(d0),"=r"(d1),"=r"(d2),"=r"(d3) : "r"(addr))
#define LDSM4T(d0,d1,d2,d3,addr) \
    asm volatile("ldmatrix.sync.aligned.m8n8.x4.trans.shared.b16 {%0,%1,%2,%3}, [%4];" \
        : "=r"(d0),"=r"(d1),"=r"(d2),"=r"(d3) : "r"(addr))

__device__ __forceinline__ void mma16816(float c[4], const uint32_t a[4],
                                         uint32_t b0, uint32_t b1) {
    asm volatile(
        "mma.sync.aligned.m16n8k16.row.col.f32.f16.f16.f32 "
        "{%0,%1,%2,%3},{%4,%5,%6,%7},{%8,%9},{%0,%1,%2,%3};"
        : "+f"(c[0]), "+f"(c[1]), "+f"(c[2]), "+f"(c[3])
        : "r"(a[0]), "r"(a[1]), "r"(a[2]), "r"(a[3]), "r"(b0), "r"(b1));
}
__device__ __forceinline__ uint32_t packh2(float lo, float hi) {
    __half2 h = __floats2half2_rn(lo, hi);
    return *reinterpret_cast<uint32_t*>(&h);
}
__device__ __forceinline__ float ex2f(float x) {
    float y; asm("ex2.approx.f32 %0, %1;" : "=f"(y) : "f"(x)); return y;
}
__device__ __forceinline__ uint32_t h2ex2(uint32_t x) {
    uint32_t y; asm("ex2.approx.f16x2 %0, %1;" : "=r"(y) : "r"(x)); return y;
}

// ---------------------------------------------------------------------------
// Fused convert: x, Wq, Wk, Wv, Wo -> half, natural layouts, one launch.
// z selects tensor; 8 elems/thread.
// ---------------------------------------------------------------------------
__global__ __launch_bounds__(256) void convert_all(const float* __restrict__ x,
                                                   const float* __restrict__ Wq,
                                                   const float* __restrict__ Wk,
                                                   const float* __restrict__ Wv,
                                                   const float* __restrict__ Wo)
{
    const int z = blockIdx.z;
    const int nblk = (z == 0) ? 2048 : 512;
    if (blockIdx.x >= nblk) return;
    const float* src = (z == 0) ? x : (z == 1) ? Wq : (z == 2) ? Wk
                     : (z == 3) ? Wv : Wo;
    __half* dst = (z == 0) ? g_xh : (z == 1) ? g_wqh : (z == 2) ? g_wkh
                : (z == 3) ? g_wvh : g_woh;
    size_t i = ((size_t)blockIdx.x * 256 + threadIdx.x) * 8;
    float4 v0 = *(const float4*)(src + i);
    float4 v1 = *(const float4*)(src + i + 4);
    uint4 o;
    o.x = packh2(v0.x, v0.y); o.y = packh2(v0.z, v0.w);
    o.z = packh2(v1.x, v1.y); o.w = packh2(v1.z, v1.w);
    *(uint4*)(&dst[i]) = o;
}

// ---------------------------------------------------------------------------
// HMMA GEMM: C[4096][1024] = A[4096][1024(K)] * B  (half in, f32 acc)
// A: [m][k] 128B rows, LDSM4 a-frags.
// B: stored k-major in gmem; smem tile = 64 k-rows x 256B (2 swizzled 128B
//    regions); b-frags via ldmatrix.trans (same recipe as flash's V path).
// 128x128 block tile, BK=64, 8 warps (2x4), warp tile 64x32,
// 2-stage cp.async, 2 CTAs/SM.
// MODE 0: A=g_xh, B=W[h][c][d] (z in {q,k,v}), out -> g_{q,k,v}h [b,h,s,d]
//         (q epilogue folds 0.125*log2e: flash softmax in log2 domain)
// MODE 1: A=g_attnh, B=Wo[k][n], out -> f32 + bias
// ---------------------------------------------------------------------------
#define GSTAGES 2
#define GEMM_SMEM (GSTAGES * 32768)   // 64 KB

template<int MODE>
__global__ __launch_bounds__(256, 2) void gemm_h(const float* __restrict__ bo,
                                                 float* __restrict__ outf)
{
    extern __shared__ __align__(16) char sm[];
    const uint32_t sb = smem_u32(sm);
    const int tid = threadIdx.x;
    const int m0 = blockIdx.y * 128, n0 = blockIdx.x * 128;
    const int z = MODE ? 0 : blockIdx.z;
    const __half* A = MODE ? g_attnh : g_xh;
    const __half* B = MODE ? g_woh : (z == 0 ? g_wqh : (z == 1 ? g_wkh : g_wvh));
    const int h0 = n0 >> 6;   // first head covered by this n-tile (MODE 0)

    float acc[4][4][4];
    #pragma unroll
    for (int i = 0; i < 4; i++)
        #pragma unroll
        for (int j = 0; j < 4; j++)
            #pragma unroll
            for (int r = 0; r < 4; r++) acc[i][j][r] = 0.f;

    const int l = tid & 31, w = tid >> 5, wm = w >> 2, wn = w & 3;
    const int arow_b = wm * 64 + (l & 7) + 8 * ((l >> 3) & 1);
    const int acb = l >> 4;
    // b-frag (trans) lane pattern
    const int trow = (l & 7) + 8 * ((l >> 3) & 1);
    const int tcb  = l >> 4;
    const int breg = wn >> 1;            // which 128B region (64-col half)
    const int bgb  = (wn & 1) * 4;       // group base within region

    auto load = [&](int buf, int k0) {
        #pragma unroll
        for (int t = 0; t < 4; t++) {
            int idx = tid + t * 256;
            // A: [m][k] rows, 128 rows x 64 halves
            int arow = idx >> 3, ac = idx & 7;
            CP16(sb + buf * 16384 + arow * 128 + ((ac ^ (arow & 7)) * 16),
                 A + (size_t)(m0 + arow) * Cn + k0 + ac * 8);
            // B: 64 k-rows x 2 regions x 8 chunks
            int brow = idx >> 4, br = (idx >> 3) & 1, bc = idx & 7;
            const __half* src;
            if (MODE)
                src = B + (size_t)(k0 + brow) * Cn + n0 + br * 64 + bc * 8;
            else
                src = B + ((size_t)(h0 + br) * Cn + (k0 + brow)) * Dh + bc * 8;
            CP16(sb + GSTAGES * 16384 + buf * 16384 + brow * 256 + br * 128
                     + ((bc ^ (brow & 7)) * 16), src);
        }
    };

    load(0, 0); CPCOMMIT();

    for (int it = 0; it < 16; it++) {
        const int buf = it & 1;
        if (it + 1 < 16) { load(buf ^ 1, (it + 1) * 64); CPCOMMIT(); cpwait<1>(); }
        else             cpwait<0>();
        __syncthreads();

        const uint32_t Ab = sb + buf * 16384;
        const uint32_t Bb = sb + GSTAGES * 16384 + buf * 16384;
        #pragma unroll
        for (int ks = 0; ks < 4; ks++) {
            uint32_t a[4][4], bf[4][2];
            #pragma unroll
            for (int mf = 0; mf < 4; mf++) {
                int r = arow_b + mf * 16;
                LDSM4(a[mf][0], a[mf][1], a[mf][2], a[mf][3],
                      Ab + r * 128 + (((ks * 2 + acb) ^ (r & 7)) * 16));
            }
            #pragma unroll
            for (int p = 0; p < 2; p++) {
                int r = ks * 16 + trow;
                int gidx = bgb + p * 2 + tcb;
                LDSM4T(bf[2*p][0], bf[2*p][1], bf[2*p+1][0], bf[2*p+1][1],
                       Bb + r * 256 + breg * 128 + ((gidx ^ (r & 7)) * 16));
            }
            #pragma unroll
            for (int mf = 0; mf < 4; mf++)
                #pragma unroll
                for (int nf = 0; nf < 4; nf++)
                    mma16816(acc[mf][nf], a[mf], bf[nf][0], bf[nf][1]);
        }
        __syncthreads();
    }

    // epilogue
    const int g = l >> 2, t2 = (l & 3) * 2;
    if (MODE == 0) {
        // q scale: 1/sqrt(D) * log2(e)
        const float sc = (z == 0) ? 0.180336881f : 1.0f;
        __half* O = (z == 0) ? g_qh : (z == 1) ? g_kh : g_vh;
        #pragma unroll
        for (int mf = 0; mf < 4; mf++) {
            int row = m0 + wm * 64 + mf * 16 + g;
            int b_ = row >> 11, s = row & (Sn - 1);
            #pragma unroll
            for (int nf = 0; nf < 4; nf++) {
                int col = n0 + wn * 32 + nf * 8 + t2;
                int h = col >> 6, d = col & 63;
                size_t i0 = (((size_t)b_ * Hh + h) * Sn + s) * Dh + d;
                *(__half2*)(O + i0) =
                    __floats2half2_rn(acc[mf][nf][0] * sc, acc[mf][nf][1] * sc);
                *(__half2*)(O + i0 + 8 * Dh) =
                    __floats2half2_rn(acc[mf][nf][2] * sc, acc[mf][nf][3] * sc);
            }
        }
    } else {
        #pragma unroll
        for (int mf = 0; mf < 4; mf++) {
            int row = m0 + wm * 64 + mf * 16 + g;
            #pragma unroll
            for (int nf = 0; nf < 4; nf++) {
                int col = n0 + wn * 32 + nf * 8 + t2;
                float b0v = bo[col], b1v = bo[col + 1];
                *(float2*)(outf + (size_t)row * Cn + col) =
                    make_float2(acc[mf][nf][0] + b0v, acc[mf][nf][1] + b1v);
                *(float2*)(outf + (size_t)(row + 8) * Cn + col) =
                    make_float2(acc[mf][nf][2] + b0v, acc[mf][nf][3] + b1v);
            }
        }
    }
}

// ---------------------------------------------------------------------------
// HMMA causal flash attention, log2-domain softmax (unchanged from R5).
// ---------------------------------------------------------------------------
#define FSTAGES 3
#define FLASH_SMEM (16384 + FSTAGES * 16384)   // 64 KB

__global__ __launch_bounds__(256) void flash_h()
{
    extern __shared__ __align__(16) char sm[];
    const uint32_t sb = smem_u32(sm);
    const int tid = threadIdx.x;
    const int l = tid & 31, w = tid >> 5;
    const int bh = blockIdx.y;
    const int qt = gridDim.x - 1 - blockIdx.x;   // heavy tiles first
    const int qs0 = qt * 128;

    const __half* Qb = g_qh + (size_t)bh * Sn * Dh;
    const __half* Kb = g_kh + (size_t)bh * Sn * Dh;
    const __half* Vb = g_vh + (size_t)bh * Sn * Dh;

    auto load_kv = [&](int buf, int ks0) {
        #pragma unroll
        for (int t = 0; t < 4; t++) {
            int idx = tid + t * 256;
            int which = idx >> 9;            // 0=K, 1=V
            int r = (idx >> 3) & 63, c = idx & 7;
            const __half* src = (which ? Vb : Kb) + (size_t)(ks0 + r) * Dh + c * 8;
            uint32_t dst = sb + 16384 + buf * 16384 + which * 8192
                         + r * 128 + ((c ^ (r & 7)) * 16);
            CP16(dst, src);
        }
    };

    const int nt = 2 * qt + 2;

    #pragma unroll
    for (int t = 0; t < 4; t++) {
        int idx = tid + t * 256;
        int row = idx >> 3, c = idx & 7;
        CP16(sb + row * 128 + ((c ^ (row & 7)) * 16),
             Qb + (size_t)(qs0 + row) * Dh + c * 8);
    }
    load_kv(0, 0);
    CPCOMMIT();
    load_kv(1, 64);
    CPCOMMIT();

    uint32_t qf[4][4];
    float o[8][4];
    #pragma unroll
    for (int i = 0; i < 8; i++)
        #pragma unroll
        for (int j = 0; j < 4; j++) o[i][j] = 0.f;
    float m0_ = -1e30f, m1_ = -1e30f, l0_ = 0.f, l1_ = 0.f;

    const int g = l >> 2, t2 = (l & 3) * 2;
    const int arow = (l & 7) + 8 * ((l >> 3) & 1);
    const int acb  = l >> 4;
    const int brow = (l & 7) + 8 * (l >> 4);
    const int bcb  = (l >> 3) & 1;
    const uint32_t ONES2 = 0x3C003C00u;

    for (int jt = 0; jt < nt; jt++) {
        cpwait<1>();
        __syncthreads();
        if (jt + 2 < nt) load_kv((jt + 2) % FSTAGES, (jt + 2) * 64);
        CPCOMMIT();

        if (jt == 0) {
            #pragma unroll
            for (int ks = 0; ks < 4; ks++) {
                int r = w * 16 + arow;
                LDSM4(qf[ks][0], qf[ks][1], qf[ks][2], qf[ks][3],
                      sb + r * 128 + (((ks * 2 + acb) ^ (r & 7)) * 16));
            }
        }
        const int buf = jt % FSTAGES;
        const uint32_t Kbase = sb + 16384 + buf * 16384;
        const uint32_t Vbase = Kbase + 8192;

        float s[8][4];
        #pragma unroll
        for (int i = 0; i < 8; i++)
            #pragma unroll
            for (int j = 0; j < 4; j++) s[i][j] = 0.f;
        #pragma unroll
        for (int ks = 0; ks < 4; ks++) {
            uint32_t kb[8][2];
            #pragma unroll
            for (int p = 0; p < 4; p++) {
                int r = p * 16 + brow;
                LDSM4(kb[2*p][0], kb[2*p][1], kb[2*p+1][0], kb[2*p+1][1],
                      Kbase + r * 128 + (((ks * 2 + bcb) ^ (r & 7)) * 16));
            }
            #pragma unroll
            for (int nf = 0; nf < 8; nf++)
                mma16816(s[nf], qf[ks], kb[nf][0], kb[nf][1]);
        }

        const int ks0 = jt * 64;
        const int rg = qs0 + w * 16 + g;
        if (jt >= nt - 2) {
            #pragma unroll
            for (int nf = 0; nf < 8; nf++) {
                int c0 = ks0 + nf * 8 + t2;
                if (c0     > rg    ) s[nf][0] = -1e30f;
                if (c0 + 1 > rg    ) s[nf][1] = -1e30f;
                if (c0     > rg + 8) s[nf][2] = -1e30f;
                if (c0 + 1 > rg + 8) s[nf][3] = -1e30f;
            }
        }

        float x0 = -1e30f, x1 = -1e30f;
        #pragma unroll
        for (int nf = 0; nf < 8; nf++) {
            x0 = fmaxf(x0, fmaxf(s[nf][0], s[nf][1]));
            x1 = fmaxf(x1, fmaxf(s[nf][2], s[nf][3]));
        }
        x0 = fmaxf(x0, __shfl_xor_sync(0xffffffffu, x0, 1));
        x0 = fmaxf(x0, __shfl_xor_sync(0xffffffffu, x0, 2));
        x1 = fmaxf(x1, __shfl_xor_sync(0xffffffffu, x1, 1));
        x1 = fmaxf(x1, __shfl_xor_sync(0xffffffffu, x1, 2));
        float mn0 = fmaxf(m0_, x0), mn1 = fmaxf(m1_, x1);
        float al0 = ex2f(m0_ - mn0), al1 = ex2f(m1_ - mn1);
        m0_ = mn0; m1_ = mn1;

        uint32_t pf[4][4];
        #pragma unroll
        for (int ki = 0; ki < 4; ki++) {
            pf[ki][0] = h2ex2(packh2(s[2*ki][0]   - mn0, s[2*ki][1]   - mn0));
            pf[ki][1] = h2ex2(packh2(s[2*ki][2]   - mn1, s[2*ki][3]   - mn1));
            pf[ki][2] = h2ex2(packh2(s[2*ki+1][0] - mn0, s[2*ki+1][1] - mn0));
            pf[ki][3] = h2ex2(packh2(s[2*ki+1][2] - mn1, s[2*ki+1][3] - mn1));
        }

        float rsac[4] = {0.f, 0.f, 0.f, 0.f};
        #pragma unroll
        for (int ki = 0; ki < 4; ki++)
            mma16816(rsac, pf[ki], ONES2, ONES2);
        l0_ = l0_ * al0 + rsac[0];
        l1_ = l1_ * al1 + rsac[2];

        #pragma unroll
        for (int df = 0; df < 8; df++) {
            o[df][0] *= al0; o[df][1] *= al0;
            o[df][2] *= al1; o[df][3] *= al1;
        }

        #pragma unroll
        for (int ki = 0; ki < 4; ki++) {
            uint32_t vb[8][2];
            #pragma unroll
            for (int p = 0; p < 4; p++) {
                int r = ki * 16 + arow;
                LDSM4T(vb[2*p][0], vb[2*p][1], vb[2*p+1][0], vb[2*p+1][1],
                       Vbase + r * 128 + (((p * 2 + acb) ^ (r & 7)) * 16));
            }
            #pragma unroll
            for (int df = 0; df < 8; df++)
                mma16816(o[df], pf[ki], vb[df][0], vb[df][1]);
        }
    }

    const float inv0 = 1.f / l0_, inv1 = 1.f / l1_;
    const int b_ = bh >> 4, h_ = bh & 15;
    const int r0 = qs0 + w * 16 + g;
    #pragma unroll
    for (int df = 0; df < 8; df++) {
        int col = h_ * 64 + df * 8 + t2;
        *(__half2*)(g_attnh + (size_t)(b_ * Sn + r0) * Cn + col) =
            __floats2half2_rn(o[df][0] * inv0, o[df][1] * inv0);
        *(__half2*)(g_attnh + (size_t)(b_ * Sn + r0 + 8) * Cn + col) =
            __floats2half2_rn(o[df][2] * inv1, o[df][3] * inv1);
    }
}

// ---------------------------------------------------------------------------
extern "C" void kernel_launch(void* const* d_in, const int* in_sizes, int n_in,
                              void* d_out, int out_size)
{
    (void)in_sizes; (void)n_in; (void)out_size;
    const float* x  = (const float*)d_in[0];
    const float* Wq = (const float*)d_in[1];
    const float* Wk = (const float*)d_in[2];
    const float* Wv = (const float*)d_in[3];
    const float* Wo = (const float*)d_in[4];
    const float* bo = (const float*)d_in[5];
    float* out = (float*)d_out;

    cudaFuncSetAttribute(gemm_h<0>, cudaFuncAttributeMaxDynamicSharedMemorySize, GEMM_SMEM);
    cudaFuncSetAttribute(gemm_h<1>, cudaFuncAttributeMaxDynamicSharedMemorySize, GEMM_SMEM);
    cudaFuncSetAttribute(flash_h,   cudaFuncAttributeMaxDynamicSharedMemorySize, FLASH_SMEM);

    convert_all<<<dim3(2048, 1, 5), 256>>>(x, Wq, Wk, Wv, Wo);
    gemm_h<0><<<dim3(Cn / 128, Mrows / 128, 3), 256, GEMM_SMEM>>>(nullptr, nullptr);
    flash_h<<<dim3(Sn / 128, Bn * Hh), 256, FLASH_SMEM>>>();
    gemm_h<1><<<dim3(Cn / 128, Mrows / 128, 1), 256, GEMM_SMEM>>>(bo, out);
}